// round 13
// baseline (speedup 1.0000x reference)
#include <cuda_runtime.h>
#include <math.h>

// ---------------- problem constants ----------------
#define cU 160
#define cL 512
#define cN 400
#define cS 16
#define cW 64
#define CVIOL 20000.0f
#define NITERS 500
#define NPOWER 30

// ---------------- grid constants ----------------
#define NB 40
#define NT 256
#define NTH (NB*NT)

// ---------------- X (primal) layout ----------------
#define OX_P   0
#define OX_RU  160
#define OX_RD  320
#define OX_PU  480
#define OX_PD  3040
#define OX_SU  5600
#define OX_SD  6000
#define XTOT   6400

// ---------------- Y (dual ineq) layout ----------------
#define OY1 0
#define OY2 160
#define OY3 320
#define OY4 832
#define OY5 1344
#define OY6 3904
#define OY7 6464
#define OY8 14656
#define YTOT 22848

// ---------------- device state (mutable: ALWAYS accessed via .cg) ----------------
__device__ __align__(16) float g_X[XTOT];
__device__ __align__(16) float g_XBP[cU];        // xbar p
__device__ __align__(16) float g_XBC[cU*cS];     // xbar (pu - pd)
__device__ __align__(16) float g_XBE[cN];        // xbar (su - sd)
__device__ __align__(16) float g_Y[YTOT];
__device__ __align__(16) float g_s78[cL*cS];
__device__ float g_s78s[cL];
__device__ float g_t[cL];
__device__ float g_z1, g_z2[cS], g_z2sum, g_tau;
__device__ float g_part_p[NB], g_part_e[NB], g_part_c[NB*cS], g_part_ss[NB];

// immutable after setup (normal loads -> L1-cached)
__device__ float g_Hg[cL*cU];
__device__ float g_HgT[cU*cL];
__device__ float g_PTT[cN*cL];
__device__ float g_c3[cL], g_c4[cL];
__device__ __align__(16) float g_b7[cL*cS];
__device__ __align__(16) float g_b8[cL*cS];
__device__ int   g_gidx[cU];
__device__ int   g_widx[cW];
__device__ float g_beq1, g_beq2[cS];

// ---------------- barrier state ----------------
__device__ unsigned g_arrive[NB*8];   // stride-8 padded arrival slots
__device__ unsigned g_epoch = 0;      // persistent round base across launches

// ---------------- cg helpers ----------------
__device__ __forceinline__ float  ldcg (const float*  p){ return __ldcg(p); }
__device__ __forceinline__ float4 ldcg4(const float4* p){ return __ldcg(p); }
__device__ __forceinline__ void   stcg (float* p, float v){ __stcg(p, v); }

// ---------------- flat-arrival grid barrier (tight spin, no sleep) ----------------
__device__ __forceinline__ void gsync(unsigned rnd) {
    __syncthreads();
    if (threadIdx.x < 32) {
        const int lane = threadIdx.x;
        if (lane == 0) {
            asm volatile("st.release.gpu.global.u32 [%0], %1;"
                         :: "l"(&g_arrive[blockIdx.x * 8]), "r"(rnd) : "memory");
        }
        const unsigned* p0 = &g_arrive[(lane)     * 8];
        const unsigned* p1 = &g_arrive[(lane + 8) * 8];
        bool ok;
        do {
            unsigned a, b;
            asm volatile("ld.acquire.gpu.global.u32 %0, [%1];" : "=r"(a) : "l"(p0) : "memory");
            asm volatile("ld.acquire.gpu.global.u32 %0, [%1];" : "=r"(b) : "l"(p1) : "memory");
            ok = ((int)(a - rnd) >= 0) && ((int)(b - rnd) >= 0);
        } while (!__all_sync(0xffffffffu, ok));
    }
    __syncthreads();
}

// ---------------- warp helpers ----------------
__device__ __forceinline__ float wallred(float v) {
#pragma unroll
    for (int o = 16; o; o >>= 1) v += __shfl_xor_sync(0xffffffffu, v, o);
    return v;
}

__device__ __forceinline__ void allred16(float (&v)[16]) {
#pragma unroll
    for (int o = 16; o; o >>= 1) {
#pragma unroll
        for (int k = 0; k < 16; k++) v[k] += __shfl_xor_sync(0xffffffffu, v[k], o);
    }
}

__device__ __forceinline__ float pick16(const float (&a)[16], int s) {
    float r = a[0];
#pragma unroll
    for (int k = 1; k < 16; k++) r = (s == k) ? a[k] : r;
    return r;
}

// dual-u fused 16-col FMA from L2 (one s78 row feeds two u accumulator sets)
__device__ __forceinline__ void fma16dual(float (&A)[16], float (&B)[16],
                                          float h0, float h1, const float4* p) {
    float4 a0 = __ldcg(p), a1 = __ldcg(p+1), a2 = __ldcg(p+2), a3 = __ldcg(p+3);
    A[0]=fmaf(h0,a0.x,A[0]);   B[0]=fmaf(h1,a0.x,B[0]);
    A[1]=fmaf(h0,a0.y,A[1]);   B[1]=fmaf(h1,a0.y,B[1]);
    A[2]=fmaf(h0,a0.z,A[2]);   B[2]=fmaf(h1,a0.z,B[2]);
    A[3]=fmaf(h0,a0.w,A[3]);   B[3]=fmaf(h1,a0.w,B[3]);
    A[4]=fmaf(h0,a1.x,A[4]);   B[4]=fmaf(h1,a1.x,B[4]);
    A[5]=fmaf(h0,a1.y,A[5]);   B[5]=fmaf(h1,a1.y,B[5]);
    A[6]=fmaf(h0,a1.z,A[6]);   B[6]=fmaf(h1,a1.z,B[6]);
    A[7]=fmaf(h0,a1.w,A[7]);   B[7]=fmaf(h1,a1.w,B[7]);
    A[8]=fmaf(h0,a2.x,A[8]);   B[8]=fmaf(h1,a2.x,B[8]);
    A[9]=fmaf(h0,a2.y,A[9]);   B[9]=fmaf(h1,a2.y,B[9]);
    A[10]=fmaf(h0,a2.z,A[10]); B[10]=fmaf(h1,a2.z,B[10]);
    A[11]=fmaf(h0,a2.w,A[11]); B[11]=fmaf(h1,a2.w,B[11]);
    A[12]=fmaf(h0,a3.x,A[12]); B[12]=fmaf(h1,a3.x,B[12]);
    A[13]=fmaf(h0,a3.y,A[13]); B[13]=fmaf(h1,a3.y,B[13]);
    A[14]=fmaf(h0,a3.z,A[14]); B[14]=fmaf(h1,a3.z,B[14]);
    A[15]=fmaf(h0,a3.w,A[15]); B[15]=fmaf(h1,a3.w,B[15]);
}

// ---------------- Phase A (homogeneous: every block 4 u + 10 n) ----------------
// u-dots: 8 warps, 2 u per warp (pair = wId>>2), l-segment = (wId&3)*128.
// combine: warps 0-3 (warp j owns u = blk*4+j), fused y1/y2/y5/y6 updates (non-POW).
// n-dots: all warps (rows blk*10+wId; warps 6,7 also rows +8,+9).
template<bool POW>
__device__ __forceinline__ void phaseA(int blk, int wId, int lane, float tau,
                                       const float* __restrict__ Cost,
                                       const float* __restrict__ Cru,
                                       const float* __restrict__ Crd,
                                       const float* __restrict__ Pmax,
                                       float* sA, float* shp, float* shc,
                                       float* sh_e, float* sh_su, float* sh_sn,
                                       float* s78s_sh)
{
    const float sig = tau;
    // stage s78s for the n-dots (used after sync1)
    for (int i = threadIdx.x; i < cL; i += NT) s78s_sh[i] = ldcg(&g_s78s[i]);
    // prefetch duals (combine warps) + z2sum (all) before the dots
    const int cu = blk*4 + wId;  // valid for wId<4
    float y5v = 0.f, y6v = 0.f, y1u = 0.f, y2u = 0.f, z1 = 0.f, z2s = 0.f;
    if (wId < 4) {
        if (lane < cS) {
            y5v = ldcg(&g_Y[OY5 + cu*cS + lane]);
            y6v = ldcg(&g_Y[OY6 + cu*cS + lane]);
            z2s = ldcg(&g_z2[lane]);
        }
        y1u = ldcg(&g_Y[OY1 + cu]); y2u = ldcg(&g_Y[OY2 + cu]);
        z1  = ldcg(&g_z1);
    }
    const float zs = ldcg(&g_z2sum);

    // ---- u-dots ----
    const int pair = wId >> 2;
    const int Lb   = (wId & 3) * 128;
    const int u0   = blk*4 + pair*2;
    float acc0[16], acc1[16];
#pragma unroll
    for (int k = 0; k < 16; k++) { acc0[k] = 0.f; acc1[k] = 0.f; }
    float t0 = 0.f, t1 = 0.f;
    const float* h0r = g_HgT + (size_t)u0 * cL + Lb;
    const float* h1r = h0r + cL;
#pragma unroll
    for (int j = 0; j < 4; j++) {
        int lo = lane + 32*j;
        int l  = Lb + lo;
        float h0 = h0r[lo], h1 = h1r[lo];          // L1-resident
        float tv = ldcg(&g_t[l]);
        t0 = fmaf(h0, tv, t0); t1 = fmaf(h1, tv, t1);
        fma16dual(acc0, acc1, h0, h1,
                  reinterpret_cast<const float4*>(g_s78 + (size_t)l * cS));
    }
    allred16(acc0); allred16(acc1);
    t0 = wallred(t0); t1 = wallred(t1);
    if (lane < 16) {
        sA[(wId*2  )*20 + lane] = pick16(acc0, lane);
        sA[(wId*2+1)*20 + lane] = pick16(acc1, lane);
    }
    if (lane == 0) { sA[(wId*2)*20 + 16] = t0; sA[(wId*2+1)*20 + 16] = t1; }
    __syncthreads();

    // ---- combine + u updates (warps 0-3; warp j owns u-local j) ----
    if (wId < 4) {
        const int pr = wId >> 1, st = wId & 1;
        const int b0 = (pr*8 + st) * 20;
        float v = 0.f;
        if (lane < 17) v = sA[b0+lane] + sA[b0+40+lane] + sA[b0+80+lane] + sA[b0+120+lane];
        float aT = __shfl_sync(0xffffffffu, v, 16);
        float aS = v;   // lanes 0..15
        float sum5 = wallred((lane < cS) ? y5v : 0.f);
        float sum6 = wallred((lane < cS) ? y6v : 0.f);
        float ssu = 0.f;
        float xb_p = 0.f, xb_ru = 0.f, xb_rd = 0.f;
        if (lane == 0) {
            float gp  = y1u - y2u + aT + z1;
            float gru = y1u - sum5;
            float grd = y2u - sum6;
            if (POW) {
                stcg(&g_X[OX_P + cu], gp); stcg(&g_X[OX_RU + cu], gru); stcg(&g_X[OX_RD + cu], grd);
                ssu += gp*gp + gru*gru + grd*grd;
                shp[wId] = gp;
            } else {
                float x = ldcg(&g_X[OX_P + cu]);
                float xn = fmaxf(x - tau*(Cost[cu] + gp), 0.f);
                xb_p = 2.f*xn - x;
                stcg(&g_X[OX_P + cu], xn); stcg(&g_XBP[cu], xb_p); shp[wId] = xb_p;
                x = ldcg(&g_X[OX_RU + cu]); xn = fmaxf(x - tau*(Cru[cu] + gru), 0.f);
                xb_ru = 2.f*xn - x; stcg(&g_X[OX_RU + cu], xn);
                x = ldcg(&g_X[OX_RD + cu]); xn = fmaxf(x - tau*(Crd[cu] + grd), 0.f);
                xb_rd = 2.f*xn - x; stcg(&g_X[OX_RD + cu], xn);
            }
        }
        if (!POW) {
            xb_ru = __shfl_sync(0xffffffffu, xb_ru, 0);
            xb_rd = __shfl_sync(0xffffffffu, xb_rd, 0);
        }
        if (lane < cS) {
            float gpu_ = y5v + aS + z2s;
            float gpd_ = y6v - aS - z2s;
            int iu = OX_PU + cu*cS + lane, id = OX_PD + cu*cS + lane;
            if (POW) {
                stcg(&g_X[iu], gpu_); stcg(&g_X[id], gpd_);
                ssu += gpu_*gpu_ + gpd_*gpd_;
                shc[wId*cS + lane] = gpu_ - gpd_;
            } else {
                float x = ldcg(&g_X[iu]); float xn = fmaxf(x - tau*gpu_, 0.f);
                float xbu = 2.f*xn - x; stcg(&g_X[iu], xn);
                x = ldcg(&g_X[id]); xn = fmaxf(x - tau*gpd_, 0.f);
                float xbd = 2.f*xn - x; stcg(&g_X[id], xn);
                stcg(&g_XBC[cu*cS + lane], xbu - xbd);
                shc[wId*cS + lane] = xbu - xbd;
                float y5n = fmaxf(y5v + sig*(xbu - xb_ru), 0.f);
                float y6n = fmaxf(y6v + sig*(xbd - xb_rd), 0.f);
                stcg(&g_Y[OY5 + cu*cS + lane], y5n);
                stcg(&g_Y[OY6 + cu*cS + lane], y6n);
            }
        }
        if (!POW && lane == 0) {
            float y1n = fmaxf(y1u + sig*(xb_p + xb_ru - Pmax[cu]), 0.f);
            float y2n = fmaxf(y2u + sig*(xb_rd - xb_p), 0.f);
            stcg(&g_Y[OY1 + cu], y1n); stcg(&g_Y[OY2 + cu], y2n);
        }
        if (POW) {
            float w = wallred(ssu);
            if (lane == 0) sh_su[wId] = w;
        }
    }

    // ---- n-dots (all warps; warps 6,7 take the two extra rows) ----
    {
        const int n1 = blk*10 + wId;
        const bool two_n = (wId >= 6);
        const int n2 = two_n ? (blk*10 + 8 + (wId - 6)) : n1;
        float a1 = 0.f, a2 = 0.f;
        const float* r1 = g_PTT + (size_t)n1 * cL;
        const float* r2 = g_PTT + (size_t)n2 * cL;
#pragma unroll 4
        for (int l = lane; l < cL; l += 32) {
            float s = s78s_sh[l];
            a1 = fmaf(r1[l], s, a1);
            a2 = fmaf(r2[l], s, a2);
        }
        a1 = wallred(a1); a2 = wallred(a2);
        if (lane == 0) {
            float agg_e = 0.f, agg_sn = 0.f;
            {
                float gsu = a1 + zs, gsd = -a1 - zs;
                if (POW) {
                    stcg(&g_X[OX_SU + n1], gsu); stcg(&g_X[OX_SD + n1], gsd);
                    agg_sn += gsu*gsu + gsd*gsd;
                    agg_e  += gsu - gsd;
                } else {
                    float x = ldcg(&g_X[OX_SU + n1]); float xn = fmaxf(x - tau*(CVIOL + gsu), 0.f);
                    float xbu = 2.f*xn - x; stcg(&g_X[OX_SU + n1], xn);
                    x = ldcg(&g_X[OX_SD + n1]); xn = fmaxf(x - tau*(CVIOL + gsd), 0.f);
                    float xbd = 2.f*xn - x; stcg(&g_X[OX_SD + n1], xn);
                    stcg(&g_XBE[n1], xbu - xbd);
                    agg_e += xbu - xbd;
                }
            }
            if (two_n) {
                float gsu = a2 + zs, gsd = -a2 - zs;
                if (POW) {
                    stcg(&g_X[OX_SU + n2], gsu); stcg(&g_X[OX_SD + n2], gsd);
                    agg_sn += gsu*gsu + gsd*gsd;
                    agg_e  += gsu - gsd;
                } else {
                    float x = ldcg(&g_X[OX_SU + n2]); float xn = fmaxf(x - tau*(CVIOL + gsu), 0.f);
                    float xbu = 2.f*xn - x; stcg(&g_X[OX_SU + n2], xn);
                    x = ldcg(&g_X[OX_SD + n2]); xn = fmaxf(x - tau*(CVIOL + gsd), 0.f);
                    float xbd = 2.f*xn - x; stcg(&g_X[OX_SD + n2], xn);
                    stcg(&g_XBE[n2], xbu - xbd);
                    agg_e += xbu - xbd;
                }
            }
            sh_e[wId]  = agg_e;
            if (POW) sh_sn[wId] = agg_sn;
        }
    }
    __syncthreads();
    if (wId == 0) {
        if (lane == 0) stcg(&g_part_p[blk], shp[0] + shp[1] + shp[2] + shp[3]);
        if (lane < cS) stcg(&g_part_c[blk*cS + lane],
                            shc[lane] + shc[cS+lane] + shc[2*cS+lane] + shc[3*cS+lane]);
        if (lane == 0) {
            float se = 0.f;
#pragma unroll
            for (int k = 0; k < 8; k++) se += sh_e[k];
            stcg(&g_part_e[blk], se);
            if (POW) {
                float ss = sh_su[0] + sh_su[1] + sh_su[2] + sh_su[3];
#pragma unroll
                for (int k = 0; k < 8; k++) ss += sh_sn[k];
                stcg(&g_part_ss[blk], ss);
            }
        }
    }
}

// ---------------- Phase B row update ----------------
template<bool POW>
__device__ __forceinline__ void rowUpdate(int l, float sig, const float (&acc)[16],
                                          float f, float pterm,
                                          float y3, float y4, float y7, float y8, int lane)
{
    float base = f + pterm;
    float y3n, y4n;
    if (POW) { y3n = f; y4n = -f; }
    else {
        y3n = fmaxf(y3 + sig*( f - g_c3[l]), 0.f);
        y4n = fmaxf(y4 + sig*(-f - g_c4[l]), 0.f);
    }
    float s78v = 0.f;
    if (lane < cS) {
        float scen = pick16(acc, lane) + base;
        float y7n, y8n;
        if (POW) { y7n = scen; y8n = -scen; }
        else {
            y7n = fmaxf(y7 + sig*( scen - g_b7[l*cS + lane]), 0.f);
            y8n = fmaxf(y8 + sig*(-scen - g_b8[l*cS + lane]), 0.f);
        }
        stcg(&g_Y[OY7 + l*cS + lane], y7n);
        stcg(&g_Y[OY8 + l*cS + lane], y8n);
        s78v = y7n - y8n;
        stcg(&g_s78[l*cS + lane], s78v);
    }
    float s78s = wallred(s78v);
    if (lane == 0) {
        stcg(&g_Y[OY3 + l], y3n);
        stcg(&g_Y[OY4 + l], y4n);
        stcg(&g_s78s[l], s78s);
        stcg(&g_t[l], y3n - y4n + s78s);
    }
}

// ---------------- Phase B (homogeneous: every block 12-13 l-rows) ----------------
// blocks 0-31: 13 rows at blk*13; blocks 32-39: 12 rows at 416+(blk-32)*12.
// warp w: rows w and w+8 (if < rl). POW: warps 4-7 also write u-y rows (scaled v).
// eq-duals: block 39 warp 7.
template<bool POW>
__device__ __forceinline__ void phaseB(int blk, int wId, int lane, float sig,
                                       const float* __restrict__ PTDF,
                                       float* dsh_t, float* sdsh, float* psh)
{
    float inv = 1.f;
    if (POW) {
        float a = ldcg(&g_part_ss[lane]) + ((lane < 8) ? ldcg(&g_part_ss[lane + 32]) : 0.f);
        a = wallred(a);
        inv = rsqrtf(a);
    }
    // ---- staging ----
    if (POW) {
        for (int c = threadIdx.x; c < (cU*cS/4); c += NT) {
            float4 a = ldcg4(reinterpret_cast<const float4*>(g_X + OX_PU) + c);
            float4 b = ldcg4(reinterpret_cast<const float4*>(g_X + OX_PD) + c);
            int u = c >> 2, s0 = (c & 3) * 4;
            dsh_t[(s0+0)*cU + u] = (a.x - b.x) * inv;
            dsh_t[(s0+1)*cU + u] = (a.y - b.y) * inv;
            dsh_t[(s0+2)*cU + u] = (a.z - b.z) * inv;
            dsh_t[(s0+3)*cU + u] = (a.w - b.w) * inv;
        }
        for (int i = threadIdx.x; i < cN; i += NT)
            sdsh[i] = (ldcg(&g_X[OX_SU + i]) - ldcg(&g_X[OX_SD + i])) * inv;
        for (int i = threadIdx.x; i < cU; i += NT)
            psh[i] = ldcg(&g_X[OX_P + i]) * inv;
    } else {
        for (int c = threadIdx.x; c < (cU*cS/4); c += NT) {
            float4 d = ldcg4(reinterpret_cast<const float4*>(g_XBC) + c);
            int u = c >> 2, s0 = (c & 3) * 4;
            dsh_t[(s0+0)*cU + u] = d.x;
            dsh_t[(s0+1)*cU + u] = d.y;
            dsh_t[(s0+2)*cU + u] = d.z;
            dsh_t[(s0+3)*cU + u] = d.w;
        }
        for (int i = threadIdx.x; i < cN; i += NT) sdsh[i] = ldcg(&g_XBE[i]);
        for (int i = threadIdx.x; i < cU; i += NT) psh[i] = ldcg(&g_XBP[i]);
    }
    __syncthreads();

    const int rl    = (blk < 32) ? 13 : 12;
    const int lbase = (blk < 32) ? blk*13 : 416 + (blk - 32)*12;
    const int l1    = lbase + wId;
    const bool two  = (wId + 8) < rl;
    const int l2    = two ? (l1 + 8) : l1;

    // prefetch duals before the dots
    float y3a = 0.f, y4a = 0.f, y7a = 0.f, y8a = 0.f;
    float y3b = 0.f, y4b = 0.f, y7b = 0.f, y8b = 0.f;
    if (!POW) {
        y3a = ldcg(&g_Y[OY3 + l1]); y4a = ldcg(&g_Y[OY4 + l1]);
        if (lane < cS) { y7a = ldcg(&g_Y[OY7 + l1*cS + lane]); y8a = ldcg(&g_Y[OY8 + l1*cS + lane]); }
        if (two) {
            y3b = ldcg(&g_Y[OY3 + l2]); y4b = ldcg(&g_Y[OY4 + l2]);
            if (lane < cS) { y7b = ldcg(&g_Y[OY7 + l2*cS + lane]); y8b = ldcg(&g_Y[OY8 + l2*cS + lane]); }
        }
    }

    float acc1[16], acc2[16];
#pragma unroll
    for (int k = 0; k < 16; k++) { acc1[k] = 0.f; acc2[k] = 0.f; }
    float f1 = 0.f, f2 = 0.f, p1 = 0.f, p2 = 0.f;
    const float* hg1 = g_Hg + (size_t)l1 * cU;
    const float* hg2 = g_Hg + (size_t)l2 * cU;
#pragma unroll
    for (int u = lane; u < cU; u += 32) {
        float ps = psh[u];
        float h1 = hg1[u], h2 = hg2[u];
        f1 = fmaf(h1, ps, f1); f2 = fmaf(h2, ps, f2);
#pragma unroll
        for (int k = 0; k < 16; k++) {
            float d = dsh_t[k*cU + u];
            acc1[k] = fmaf(h1, d, acc1[k]);
            acc2[k] = fmaf(h2, d, acc2[k]);
        }
    }
    const float* pf1 = PTDF + (size_t)l1 * cN;
    const float* pf2 = PTDF + (size_t)l2 * cN;
#pragma unroll 2
    for (int n = lane; n < cN; n += 32) {
        float s = sdsh[n];
        p1 = fmaf(pf1[n], s, p1);
        p2 = fmaf(pf2[n], s, p2);
    }
    allred16(acc1); f1 = wallred(f1); p1 = wallred(p1);
    rowUpdate<POW>(l1, sig, acc1, f1, p1, y3a, y4a, y7a, y8a, lane);
    if (two) {
        allred16(acc2); f2 = wallred(f2); p2 = wallred(p2);
        rowUpdate<POW>(l2, sig, acc2, f2, p2, y3b, y4b, y7b, y8b, lane);
    }

    // POW: u-y rows (A(v) elementwise rows), warps 4-7, one u each
    if (POW && wId >= 4) {
        const int u = blk*4 + (wId - 4);
        float ru = ldcg(&g_X[OX_RU + u]) * inv;
        float rd = ldcg(&g_X[OX_RD + u]) * inv;
        if (lane == 0) {
            float p = ldcg(&g_X[OX_P + u]) * inv;
            stcg(&g_Y[OY1 + u], p + ru);
            stcg(&g_Y[OY2 + u], rd - p);
        }
        if (lane < cS) {
            float pu = ldcg(&g_X[OX_PU + u*cS + lane]) * inv;
            float pd = ldcg(&g_X[OX_PD + u*cS + lane]) * inv;
            stcg(&g_Y[OY5 + u*cS + lane], pu - ru);
            stcg(&g_Y[OY6 + u*cS + lane], pd - rd);
        }
    }

    // equality duals: block 39 warp 7
    if (blk == NB-1 && wId == 7) {
        float sp = ldcg(&g_part_p[lane]) + ((lane < 8) ? ldcg(&g_part_p[lane + 32]) : 0.f);
        sp = wallred(sp);
        float se = ldcg(&g_part_e[lane]) + ((lane < 8) ? ldcg(&g_part_e[lane + 32]) : 0.f);
        se = wallred(se);
        int s = lane & 15, h = lane >> 4;
        float sc = 0.f;
#pragma unroll
        for (int b = h*20; b < h*20 + 20; b++) sc += ldcg(&g_part_c[b*cS + s]);
        sc += __shfl_xor_sync(0xffffffffu, sc, 16);
        float ae2 = sc + se;
        float z2n = 0.f;
        if (lane < cS) {
            z2n = POW ? (ae2 * inv) : (ldcg(&g_z2[lane]) + sig*(ae2 - g_beq2[lane]));
            stcg(&g_z2[lane], z2n);
        }
        float zsum = wallred((lane < cS) ? z2n : 0.f);
        if (lane == 0) {
            float z1n = POW ? (sp * inv) : (ldcg(&g_z1) + sig*(sp - g_beq1));
            stcg(&g_z1, z1n);
            stcg(&g_z2sum, zsum);
        }
    }
}

// ---------------- main persistent kernel ----------------
__global__ void __launch_bounds__(NT, 1)
opf_kernel(const float* __restrict__ w_scen, const float* __restrict__ Pmax,
           const float* __restrict__ Cost, const float* __restrict__ Cru,
           const float* __restrict__ Crd, const float* __restrict__ PTDF,
           const float* __restrict__ node_G, const float* __restrict__ node_W,
           const float* __restrict__ Pd, const float* __restrict__ w_exp,
           const float* __restrict__ Cap, float* __restrict__ out)
{
    __shared__ __align__(16) float dsh_t[cS*cU];     // 10.2 KB (phase B)
    __shared__ float sdsh[cN];
    __shared__ float psh[cU];
    __shared__ float s78s_sh[cL];
    __shared__ float sA[16*20];
    __shared__ float shp[4], shc[4*cS], sh_e[8], sh_su[4], sh_sn[8];

    const int blk  = blockIdx.x;
    const int tid  = blk * NT + threadIdx.x;
    const int wId  = threadIdx.x >> 5;
    const int lane = threadIdx.x & 31;
    const int gw   = blk * 8 + wId;   // 0..319
    unsigned rnd;
    {
        unsigned e;
        asm volatile("ld.global.cg.u32 %0, [%1];" : "=r"(e) : "l"(&g_epoch));
        rnd = e;
    }

    // ---- setup 1: index extraction + equality rhs ----
    if (gw < cU) {
        int u = gw, f = -1;
        for (int n = lane; n < cN; n += 32)
            if (node_G[n * cU + u] != 0.f) f = n;
#pragma unroll
        for (int o = 16; o; o >>= 1) f = max(f, __shfl_xor_sync(0xffffffffu, f, o));
        if (lane == 0) __stcg(&g_gidx[u], f);
    } else if (gw < cU + cW) {
        int w = gw - cU, f = -1;
        for (int n = lane; n < cN; n += 32)
            if (node_W[n * cW + w] != 0.f) f = n;
#pragma unroll
        for (int o = 16; o; o >>= 1) f = max(f, __shfl_xor_sync(0xffffffffu, f, o));
        if (lane == 0) __stcg(&g_widx[w], f);
    } else if (gw == cU + cW) {
        float a = 0.f;
        for (int n = lane; n < cN; n += 32) a += Pd[n];
        for (int w = lane; w < cW; w += 32) a -= w_exp[w];
        a = wallred(a);
        if (lane == 0) stcg(&g_beq1, a);
    } else if (gw > cU + cW && gw <= cU + cW + cS) {
        int s = gw - (cU + cW + 1);
        float a = 0.f;
        for (int w = lane; w < cW; w += 32) a += w_scen[s * cW + w];
        a = wallred(a);
        if (lane == 0) stcg(&g_beq2[s], -a);
    }
    gsync(++rnd);

    // ---- setup 2: materialize matrices, rhs vectors, init power-iter state ----
    for (int i = tid; i < cL * cU; i += NTH) {
        int l = i / cU, u = i - l * cU;
        float v = PTDF[l * cN + __ldcg(&g_gidx[u])];
        g_Hg[l * cU + u] = v;
        g_HgT[u * cL + l] = v;
    }
    for (int i = tid; i < cN * cL; i += NTH) {
        int n = i >> 9, l = i & (cL - 1);
        g_PTT[i] = PTDF[l * cN + n];
    }
    for (int l = gw; l < cL; l += NB*8) {
        const float* pr = PTDF + l * cN;
        float a = 0.f;
        for (int n = lane; n < cN; n += 32) a -= pr[n] * Pd[n];
        float hw0 = pr[__ldcg(&g_widx[lane])];
        float hw1 = pr[__ldcg(&g_widx[lane + 32])];
        a += hw0 * w_exp[lane] + hw1 * w_exp[lane + 32];
        float cf = wallred(a);
        float cap = Cap[l];
        float c3 = cap - cf, c4 = cap + cf;
        if (lane == 0) { g_c3[l] = c3; g_c4[l] = c4; }
        float bws = 0.f;
#pragma unroll 4
        for (int w = 0; w < 32; w++) {
            float h0 = __shfl_sync(0xffffffffu, hw0, w);
            float h1 = __shfl_sync(0xffffffffu, hw1, w);
            if (lane < cS)
                bws += h0 * w_scen[lane * cW + w] + h1 * w_scen[lane * cW + w + 32];
        }
        if (lane < cS) {
            g_b7[l * cS + lane] = c3 - bws;
            g_b8[l * cS + lane] = c4 + bws;
        }
    }
    // init v0 = ones + its eq partials (sum p per block = 4)
    for (int i = tid; i < XTOT; i += NTH) stcg(&g_X[i], 1.f);
    if (tid < NB) {
        stcg(&g_part_ss[tid], (tid == 0) ? 1.f : 0.f);
        stcg(&g_part_e[tid], 0.f);
        stcg(&g_part_p[tid], 4.f);
    }
    for (int i = tid; i < NB*cS; i += NTH) stcg(&g_part_c[i], 0.f);
    gsync(++rnd);

    // ---- power iteration for ||A|| (31 fused B/A pairs; norm folded into B) ----
#pragma unroll 1
    for (int it = 0; it <= NPOWER; it++) {
        phaseB<true>(blk, wId, lane, 0.f, PTDF, dsh_t, sdsh, psh);
        gsync(++rnd);
        phaseA<true>(blk, wId, lane, 0.f, Cost, Cru, Crd, Pmax,
                     sA, shp, shc, sh_e, sh_su, sh_sn, s78s_sh);
        gsync(++rnd);
    }

    // ---- reset state + compute tau ----
    for (int i = tid; i < XTOT; i += NTH) stcg(&g_X[i], 0.f);
    for (int i = tid; i < cU; i += NTH) stcg(&g_XBP[i], 0.f);
    for (int i = tid; i < cU*cS; i += NTH) stcg(&g_XBC[i], 0.f);
    for (int i = tid; i < cN; i += NTH) stcg(&g_XBE[i], 0.f);
    for (int i = tid; i < YTOT; i += NTH) stcg(&g_Y[i], 0.f);
    for (int i = tid; i < cL * cS; i += NTH) stcg(&g_s78[i], 0.f);
    for (int i = tid; i < cL; i += NTH) { stcg(&g_s78s[i], 0.f); stcg(&g_t[i], 0.f); }
    if (tid == 0) {
        float a = 0.f;
        for (int b = 0; b < NB; b++) a += ldcg(&g_part_ss[b]);
        float Lop = sqrtf(sqrtf(a));
        stcg(&g_tau, 0.9f / Lop);
        stcg(&g_z1, 0.f); stcg(&g_z2sum, 0.f);
    }
    if (tid < cS) stcg(&g_z2[tid], 0.f);
    gsync(++rnd);

    const float tau = ldcg(&g_tau);

    // ---- PDHG main loop (last iteration's phase B is output-irrelevant: skip it) ----
#pragma unroll 1
    for (int it = 0; it < NITERS-1; it++) {
        phaseA<false>(blk, wId, lane, tau, Cost, Cru, Crd, Pmax,
                      sA, shp, shc, sh_e, sh_su, sh_sn, s78s_sh);
        gsync(++rnd);
        phaseB<false>(blk, wId, lane, tau, PTDF, dsh_t, sdsh, psh);
        gsync(++rnd);
    }
    phaseA<false>(blk, wId, lane, tau, Cost, Cru, Crd, Pmax,
                  sA, shp, shc, sh_e, sh_su, sh_sn, s78s_sh);
    gsync(++rnd);

    // ---- output ----
    {
        const int rl    = (blk < 32) ? 13 : 12;
        const int lbase = (blk < 32) ? blk*13 : 416 + (blk - 32)*12;
#pragma unroll 1
        for (int r = wId; r < rl; r += 8) {
            int l = lbase + r;
            const float* hr = g_Hg + (size_t)l * cU;
            float a = 0.f;
            for (int u = lane; u < cU; u += 32) a = fmaf(hr[u], ldcg(&g_X[OX_P + u]), a);
            a = wallred(a);
            if (lane == 0) {
                out[5600 + l] = g_c3[l] - a;   // f_up = Cap - flow
                out[6112 + l] = g_c4[l] + a;   // f_down = Cap + flow
            }
        }
        if (wId < 4) {
            int u = blk*4 + wId;
            if (lane == 0) {
                out[u]       = ldcg(&g_X[OX_P + u]);
                out[160 + u] = ldcg(&g_X[OX_RU + u]);
                out[320 + u] = ldcg(&g_X[OX_RD + u]);
            }
            if (lane < cS) {
                out[480 + u*cS + lane]  = ldcg(&g_X[OX_PU + u*cS + lane]);
                out[3040 + u*cS + lane] = ldcg(&g_X[OX_PD + u*cS + lane]);
            }
        }
        if (blk == 0 && wId == 7) {
            float a = 0.f;
            for (int i = lane; i < cU; i += 32)
                a += Cost[i] * ldcg(&g_X[OX_P + i]) + Cru[i] * ldcg(&g_X[OX_RU + i])
                   + Crd[i] * ldcg(&g_X[OX_RD + i]);
            for (int i = lane; i < cN; i += 32)
                a += CVIOL * (ldcg(&g_X[OX_SU + i]) + ldcg(&g_X[OX_SD + i]));
            a = wallred(a);
            if (lane == 0) out[6624] = a;
        }
    }

    // persist the barrier epoch for the next (stream-ordered) launch
    if (blk == 0 && threadIdx.x == 0) {
        asm volatile("st.global.cg.u32 [%0], %1;" :: "l"(&g_epoch), "r"(rnd) : "memory");
    }
}

extern "C" void kernel_launch(void* const* d_in, const int* in_sizes, int n_in,
                              void* d_out, int out_size) {
    const float* w_scen = (const float*)d_in[0];
    const float* Pmax   = (const float*)d_in[1];
    const float* Cost   = (const float*)d_in[2];
    const float* Cru    = (const float*)d_in[3];
    const float* Crd    = (const float*)d_in[4];
    const float* PTDF   = (const float*)d_in[5];
    const float* node_G = (const float*)d_in[6];
    const float* node_W = (const float*)d_in[7];
    // d_in[8] = node_L (identity, unused)
    const float* Pd     = (const float*)d_in[9];
    const float* w_exp  = (const float*)d_in[10];
    const float* Cap    = (const float*)d_in[11];
    float* out = (float*)d_out;
    (void)in_sizes; (void)n_in; (void)out_size;

    opf_kernel<<<NB, NT>>>(w_scen, Pmax, Cost, Cru, Crd, PTDF,
                           node_G, node_W, Pd, w_exp, Cap, out);
}

// round 14
// speedup vs baseline: 1.2739x; 1.2739x over previous
#include <cuda_runtime.h>
#include <math.h>

// ---------------- problem constants ----------------
#define cU 160
#define cL 512
#define cN 400
#define cS 16
#define cW 64
#define CVIOL 20000.0f
#define NITERS 500
#define NPOWER 30

// ---------------- grid constants ----------------
#define NB 132
#define NT 256
#define NTH (NB*NT)

// ---------------- global X layout (output staging only) ----------------
#define OX_P   0
#define OX_RU  160
#define OX_RD  320
#define OX_PU  480
#define OX_PD  3040
#define OX_SU  5600
#define OX_SD  6000
#define XTOT   6400

// ---------------- device state (mutable: ALWAYS accessed via .cg) ----------------
__device__ __align__(16) float g_X[XTOT];        // final output staging only
__device__ __align__(16) float g_XBP[cU];        // exchanged: xbar p (or v.p)
__device__ __align__(16) float g_XBC[cU*cS];     // exchanged: xbar (pu-pd)
__device__ __align__(16) float g_XBE[cN];        // exchanged: xbar (su-sd)
__device__ __align__(16) float g_s78[cL*cS];     // exchanged: y7-y8
__device__ float g_s78s[cL];
__device__ float g_t[cL];
__device__ float g_z1, g_z2[cS], g_z2sum, g_tau;
__device__ float g_part_p[NB], g_part_e[NB], g_part_c[80*cS], g_part_ss[NB];

// immutable after setup (normal loads -> L1-cached)
__device__ float g_Hg[cL*cU];
__device__ float g_HgT[cU*cL];
__device__ float g_PTT[cN*cL];
__device__ float g_c3[cL], g_c4[cL];
__device__ __align__(16) float g_b7[cL*cS];
__device__ __align__(16) float g_b8[cL*cS];
__device__ int   g_gidx[cU];
__device__ int   g_widx[cW];
__device__ float g_beq1, g_beq2[cS];

// ---------------- barrier state ----------------
__device__ unsigned g_arrive[NB*8];
__device__ unsigned g_epoch = 0;

// ---------------- cg helpers ----------------
__device__ __forceinline__ float  ldcg (const float*  p){ return __ldcg(p); }
__device__ __forceinline__ float4 ldcg4(const float4* p){ return __ldcg(p); }
__device__ __forceinline__ void   stcg (float* p, float v){ __stcg(p, v); }

// ---------------- flat-arrival grid barrier ----------------
__device__ __forceinline__ void gsync(unsigned rnd) {
    __syncthreads();
    if (threadIdx.x < 32) {
        const int lane = threadIdx.x;
        if (lane == 0) {
            asm volatile("st.release.gpu.global.u32 [%0], %1;"
                         :: "l"(&g_arrive[blockIdx.x * 8]), "r"(rnd) : "memory");
        }
        const unsigned* p0 = &g_arrive[(lane)              * 8];
        const unsigned* p1 = &g_arrive[(lane + 32)         * 8];
        const unsigned* p2 = &g_arrive[(lane + 64)         * 8];
        const unsigned* p3 = &g_arrive[(lane + 96)         * 8];
        const unsigned* p4 = &g_arrive[(128 + (lane & 3))  * 8];
        for (;;) {
            unsigned a, b, c, d, e;
            asm volatile("ld.acquire.gpu.global.u32 %0, [%1];" : "=r"(a) : "l"(p0) : "memory");
            asm volatile("ld.acquire.gpu.global.u32 %0, [%1];" : "=r"(b) : "l"(p1) : "memory");
            asm volatile("ld.acquire.gpu.global.u32 %0, [%1];" : "=r"(c) : "l"(p2) : "memory");
            asm volatile("ld.acquire.gpu.global.u32 %0, [%1];" : "=r"(d) : "l"(p3) : "memory");
            asm volatile("ld.acquire.gpu.global.u32 %0, [%1];" : "=r"(e) : "l"(p4) : "memory");
            bool ok = ((int)(a - rnd) >= 0) && ((int)(b - rnd) >= 0) &&
                      ((int)(c - rnd) >= 0) && ((int)(d - rnd) >= 0) &&
                      ((int)(e - rnd) >= 0);
            if (__all_sync(0xffffffffu, ok)) break;
            __nanosleep(40);
        }
    }
    __syncthreads();
}

// ---------------- warp helpers ----------------
__device__ __forceinline__ float wallred(float v) {
#pragma unroll
    for (int o = 16; o; o >>= 1) v += __shfl_xor_sync(0xffffffffu, v, o);
    return v;
}

__device__ __forceinline__ void allred16(float (&v)[16]) {
#pragma unroll
    for (int o = 16; o; o >>= 1) {
#pragma unroll
        for (int k = 0; k < 16; k++) v[k] += __shfl_xor_sync(0xffffffffu, v[k], o);
    }
}

__device__ __forceinline__ float pick16(const float (&a)[16], int s) {
    float r = a[0];
#pragma unroll
    for (int k = 1; k < 16; k++) r = (s == k) ? a[k] : r;
    return r;
}

// transposed smem read: buf[k*stride + idx]
__device__ __forceinline__ void fma16sh_t(float (&acc)[16], float h,
                                          const float* base, int stride) {
#pragma unroll
    for (int k = 0; k < 16; k++) acc[k] = fmaf(h, base[k * stride], acc[k]);
}

// ---------------- persistent per-block state (smem) ----------------
struct PState {
    float xp[2], xru[2], xrd[2];
    float xpu[2][cS], xpd[2][cS];
    float y1[2], y2[2];
    float y5[2][cS], y6[2][cS];
    float y3[4], y4[4];
    float y7[4][cS], y8[4][cS];
};

// ---------------- Phase A ----------------
// u-part: blocks 0..79 (2 u/block, 4 warps/u, s78 staged into smem transposed).
// n-part: blocks 80..131 (<=1 row/warp, state in registers xsu/xsd).
template<bool POW>
__device__ __forceinline__ void phaseA(int blk, int wId, int lane, float tau,
                                       const float* __restrict__ Cost,
                                       const float* __restrict__ Cru,
                                       const float* __restrict__ Crd,
                                       const float* __restrict__ Pmax,
                                       float* uBuf, float* sA, float* shp, float* shc,
                                       float* sh8, float* sh8b, float* s78s_sh,
                                       PState* P, float& xsu, float& xsd)
{
    const float sig = tau;
    if (blk < 80) {
        // ---- stage s78 (transposed [s][l]) and t into smem ----
        float* s78t = uBuf;            // 16*512
        float* tsm  = uBuf + cS*cL;    // 512
        for (int c = threadIdx.x; c < cL*4; c += NT) {
            float4 a = ldcg4(reinterpret_cast<const float4*>(g_s78) + c);
            int l = c >> 2, s0 = (c & 3) * 4;
            s78t[(s0+0)*cL + l] = a.x;
            s78t[(s0+1)*cL + l] = a.y;
            s78t[(s0+2)*cL + l] = a.z;
            s78t[(s0+3)*cL + l] = a.w;
        }
        for (int i = threadIdx.x; i < cL; i += NT) tsm[i] = ldcg(&g_t[i]);
        __syncthreads();

        // ---- u-dot: warp quad (wId>>2) owns u, segment (wId&3)*128 ----
        const int iu = wId >> 2;
        const int u  = 2*blk + iu;
        const int Lb = (wId & 3) * 128;
        float accT = 0.f;
        float acc[16];
#pragma unroll
        for (int k = 0; k < 16; k++) acc[k] = 0.f;
        const float* hr = g_HgT + (size_t)u * cL + Lb;
#pragma unroll
        for (int j = 0; j < 4; j++) {
            int lo = lane + 32*j;
            int l  = Lb + lo;
            float h = hr[lo];                     // L1-resident
            accT = fmaf(h, tsm[l], accT);
            fma16sh_t(acc, h, s78t + l, cL);
        }
        accT = wallred(accT);
        allred16(acc);
        if (lane < 16) sA[wId*17 + lane] = pick16(acc, lane);
        if (lane == 0) sA[wId*17 + 16] = accT;
        __syncthreads();

        // ---- combine + update (warps 0 and 4) ----
        if ((wId & 3) == 0) {
            const int b0 = (iu*4) * 17;
            float aT = sA[b0+16] + sA[b0+17+16] + sA[b0+34+16] + sA[b0+51+16];
            float aS = 0.f;
            if (lane < 16) aS = sA[b0+lane] + sA[b0+17+lane] + sA[b0+34+lane] + sA[b0+51+lane];
            float y5v = (lane < cS) ? P->y5[iu][lane] : 0.f;
            float y6v = (lane < cS) ? P->y6[iu][lane] : 0.f;
            float z2s = (lane < cS) ? ldcg(&g_z2[lane]) : 0.f;
            float sum5 = wallred(y5v);
            float sum6 = wallred(y6v);
            float y1u = P->y1[iu], y2u = P->y2[iu];
            float z1 = ldcg(&g_z1);
            float ssu = 0.f;
            float xb_p = 0.f, xb_ru = 0.f, xb_rd = 0.f;
            if (lane == 0) {
                float gp  = y1u - y2u + aT + z1;
                float gru = y1u - sum5;
                float grd = y2u - sum6;
                if (POW) {
                    P->xp[iu] = gp; P->xru[iu] = gru; P->xrd[iu] = grd;
                    stcg(&g_XBP[u], gp);
                    ssu += gp*gp + gru*gru + grd*grd;
                    shp[iu] = gp;
                } else {
                    float x = P->xp[iu];
                    float xn = fmaxf(x - tau*(Cost[u] + gp), 0.f);
                    xb_p = 2.f*xn - x;
                    P->xp[iu] = xn; stcg(&g_XBP[u], xb_p); shp[iu] = xb_p;
                    x = P->xru[iu]; xn = fmaxf(x - tau*(Cru[u] + gru), 0.f);
                    xb_ru = 2.f*xn - x; P->xru[iu] = xn;
                    x = P->xrd[iu]; xn = fmaxf(x - tau*(Crd[u] + grd), 0.f);
                    xb_rd = 2.f*xn - x; P->xrd[iu] = xn;
                }
            }
            if (!POW) {
                xb_ru = __shfl_sync(0xffffffffu, xb_ru, 0);
                xb_rd = __shfl_sync(0xffffffffu, xb_rd, 0);
            }
            if (lane < cS) {
                float gpu_ = y5v + aS + z2s;
                float gpd_ = y6v - aS - z2s;
                if (POW) {
                    P->xpu[iu][lane] = gpu_; P->xpd[iu][lane] = gpd_;
                    stcg(&g_XBC[u*cS + lane], gpu_ - gpd_);
                    ssu += gpu_*gpu_ + gpd_*gpd_;
                    shc[iu*cS + lane] = gpu_ - gpd_;
                } else {
                    float x = P->xpu[iu][lane]; float xn = fmaxf(x - tau*gpu_, 0.f);
                    float xbu = 2.f*xn - x; P->xpu[iu][lane] = xn;
                    x = P->xpd[iu][lane]; xn = fmaxf(x - tau*gpd_, 0.f);
                    float xbd = 2.f*xn - x; P->xpd[iu][lane] = xn;
                    stcg(&g_XBC[u*cS + lane], xbu - xbd);
                    shc[iu*cS + lane] = xbu - xbd;
                    P->y5[iu][lane] = fmaxf(y5v + sig*(xbu - xb_ru), 0.f);
                    P->y6[iu][lane] = fmaxf(y6v + sig*(xbd - xb_rd), 0.f);
                }
            }
            if (!POW && lane == 0) {
                P->y1[iu] = fmaxf(y1u + sig*(xb_p + xb_ru - Pmax[u]), 0.f);
                P->y2[iu] = fmaxf(y2u + sig*(xb_rd - xb_p), 0.f);
            }
            if (POW) {
                float w = wallred(ssu);
                if (lane == 0) sh8[iu] = w;
            }
        }
        __syncthreads();
        if (wId == 0) {
            if (lane == 0) stcg(&g_part_p[blk], shp[0] + shp[1]);
            if (lane < cS) stcg(&g_part_c[blk*cS + lane], shc[lane] + shc[cS + lane]);
            if (POW && lane == 0) stcg(&g_part_ss[blk], sh8[0] + sh8[1]);
        }
    } else {
        for (int i = threadIdx.x; i < cL; i += NT) s78s_sh[i] = ldcg(&g_s78s[i]);
        __syncthreads();
        const int wn = (blk - 80)*8 + wId;   // 0..415, active < 400
        float agg_e = 0.f, agg_ss = 0.f;
        if (wn < cN) {
            float zs = ldcg(&g_z2sum);
            float a0 = 0.f;
            const float* r0 = g_PTT + (size_t)wn * cL;
#pragma unroll 4
            for (int l = lane; l < cL; l += 32) a0 = fmaf(r0[l], s78s_sh[l], a0);
            a0 = wallred(a0);
            if (lane == 0) {
                float gsu = a0 + zs, gsd = -a0 - zs;
                if (POW) {
                    xsu = gsu; xsd = gsd;
                    stcg(&g_XBE[wn], gsu - gsd);
                    agg_ss = gsu*gsu + gsd*gsd;
                    agg_e  = gsu - gsd;
                } else {
                    float x = xsu; float xn = fmaxf(x - tau*(CVIOL + gsu), 0.f);
                    float xbu = 2.f*xn - x; xsu = xn;
                    x = xsd; xn = fmaxf(x - tau*(CVIOL + gsd), 0.f);
                    float xbd = 2.f*xn - x; xsd = xn;
                    stcg(&g_XBE[wn], xbu - xbd);
                    agg_e = xbu - xbd;
                }
            }
        }
        if (lane == 0) { sh8[wId] = agg_e; sh8b[wId] = agg_ss; }
        __syncthreads();
        if (wId == 0 && lane == 0) {
            float se = 0.f, ss = 0.f;
#pragma unroll
            for (int k = 0; k < 8; k++) { se += sh8[k]; ss += sh8b[k]; }
            stcg(&g_part_e[blk], se);
            if (POW) stcg(&g_part_ss[blk], ss);
        }
    }
}

// ---------------- Phase B ----------------
// l-part: blocks 0..127, 4 l/block, 2 warps/l. Dual state in smem P.
// POW: u-owner blocks (0..79) also write their u-y rows; eq-duals: blk 128 warp 7.
template<bool POW>
__device__ __forceinline__ void phaseB(int blk, int wId, int lane, float sig,
                                       const float* __restrict__ PTDF,
                                       float* uBuf, float* sdsh, float* psh, float* sB,
                                       PState* P)
{
    float inv = 1.f;
    if (POW) {
        float a = ldcg(&g_part_ss[lane]) + ldcg(&g_part_ss[lane + 32])
                + ldcg(&g_part_ss[lane + 64]) + ldcg(&g_part_ss[lane + 96])
                + ((lane < 4) ? ldcg(&g_part_ss[128 + lane]) : 0.f);
        a = wallred(a);
        inv = rsqrtf(a);
    }
    if (blk < 128) {
        float* dsh_t = uBuf;   // [16][160]
        for (int c = threadIdx.x; c < (cU*cS/4); c += NT) {
            float4 d = ldcg4(reinterpret_cast<const float4*>(g_XBC) + c);
            int u = c >> 2, s0 = (c & 3) * 4;
            dsh_t[(s0+0)*cU + u] = d.x * inv;
            dsh_t[(s0+1)*cU + u] = d.y * inv;
            dsh_t[(s0+2)*cU + u] = d.z * inv;
            dsh_t[(s0+3)*cU + u] = d.w * inv;
        }
        for (int i = threadIdx.x; i < cN; i += NT) sdsh[i] = ldcg(&g_XBE[i]) * inv;
        for (int i = threadIdx.x; i < cU; i += NT) psh[i] = ldcg(&g_XBP[i]) * inv;
        __syncthreads();

        const int r    = wId >> 1;           // local row 0..3
        const int l    = blk*4 + r;
        const int half = wId & 1;

        float accF = 0.f, accP = 0.f;
        float acc[16];
#pragma unroll
        for (int k = 0; k < 16; k++) acc[k] = 0.f;
        const float* hg = g_Hg + (size_t)l * cU;
        const int u0 = half * 80;
        for (int u = u0 + lane; u < u0 + 80; u += 32) {
            float h = hg[u];
            accF = fmaf(h, psh[u], accF);
            fma16sh_t(acc, h, dsh_t + u, cU);
        }
        const float* pr = PTDF + (size_t)l * cN;
        const int n0 = half * 200;
#pragma unroll 2
        for (int n = n0 + lane; n < n0 + 200; n += 32) accP = fmaf(pr[n], sdsh[n], accP);
        accF = wallred(accF);
        accP = wallred(accP);
        allred16(acc);
        if (lane < 16) sB[wId*19 + lane] = pick16(acc, lane);
        if (lane == 0) { sB[wId*19 + 16] = accF; sB[wId*19 + 17] = accP; }
        __syncthreads();
        if (half == 0) {
            float fp = sB[wId*19 + 16] + sB[(wId+1)*19 + 16];
            float aP = sB[wId*19 + 17] + sB[(wId+1)*19 + 17];
            float aS = (lane < 16) ? (sB[wId*19 + lane] + sB[(wId+1)*19 + lane]) : 0.f;
            float base = fp + aP;
            float y3n, y4n;
            if (POW) { y3n = fp; y4n = -fp; }
            else {
                y3n = fmaxf(P->y3[r] + sig*( fp - g_c3[l]), 0.f);
                y4n = fmaxf(P->y4[r] + sig*(-fp - g_c4[l]), 0.f);
            }
            float s78v = 0.f;
            if (lane < cS) {
                float scen = aS + base;
                float y7n, y8n;
                if (POW) { y7n = scen; y8n = -scen; }
                else {
                    y7n = fmaxf(P->y7[r][lane] + sig*( scen - g_b7[l*cS + lane]), 0.f);
                    y8n = fmaxf(P->y8[r][lane] + sig*(-scen - g_b8[l*cS + lane]), 0.f);
                }
                P->y7[r][lane] = y7n;
                P->y8[r][lane] = y8n;
                s78v = y7n - y8n;
                stcg(&g_s78[l*cS + lane], s78v);
            }
            float s78s = wallred(s78v);
            if (lane == 0) {
                P->y3[r] = y3n;
                P->y4[r] = y4n;
                stcg(&g_s78s[l], s78s);
                stcg(&g_t[l], y3n - y4n + s78s);
            }
        }
    }
    // POW: owner blocks write their u-y rows from smem v (scaled)
    if (POW && blk < 80 && (wId & 3) == 0) {
        const int iu = wId >> 2;
        float p  = P->xp[iu]  * inv;
        float ru = P->xru[iu] * inv;
        float rd = P->xrd[iu] * inv;
        if (lane == 0) { P->y1[iu] = p + ru; P->y2[iu] = rd - p; }
        if (lane < cS) {
            P->y5[iu][lane] = P->xpu[iu][lane] * inv - ru;
            P->y6[iu][lane] = P->xpd[iu][lane] * inv - rd;
        }
    }
    // equality duals: block 128 warp 7 (idle in l-work)
    if (blk == 128 && wId == 7) {
        float sp = 0.f;
        for (int b = lane; b < 80; b += 32) sp += ldcg(&g_part_p[b]);
        sp = wallred(sp);
        float se = 0.f;
        for (int b = 80 + lane; b < NB; b += 32) se += ldcg(&g_part_e[b]);
        se = wallred(se);
        int s = lane & 15, h = lane >> 4;
        float sc = 0.f;
#pragma unroll
        for (int b = h*40; b < h*40 + 40; b++) sc += ldcg(&g_part_c[b*cS + s]);
        sc += __shfl_xor_sync(0xffffffffu, sc, 16);
        float ae2 = sc + se;
        float z2n = 0.f;
        if (lane < cS) {
            z2n = POW ? (ae2 * inv) : (ldcg(&g_z2[lane]) + sig*(ae2 - g_beq2[lane]));
            stcg(&g_z2[lane], z2n);
        }
        float zsum = wallred((lane < cS) ? z2n : 0.f);
        if (lane == 0) {
            float z1n = POW ? (sp * inv) : (ldcg(&g_z1) + sig*(sp - g_beq1));
            stcg(&g_z1, z1n);
            stcg(&g_z2sum, zsum);
        }
    }
}

// ---------------- state init helper ----------------
__device__ __forceinline__ void initP(PState* P, float v, float& xsu, float& xsd) {
    if (threadIdx.x < cS) {
        int s = threadIdx.x;
#pragma unroll
        for (int iu = 0; iu < 2; iu++) {
            P->xpu[iu][s] = v; P->xpd[iu][s] = v;
            P->y5[iu][s] = 0.f; P->y6[iu][s] = 0.f;
        }
#pragma unroll
        for (int r = 0; r < 4; r++) { P->y7[r][s] = 0.f; P->y8[r][s] = 0.f; }
    }
    if (threadIdx.x >= 32 && threadIdx.x < 34) {
        int iu = threadIdx.x - 32;
        P->xp[iu] = v; P->xru[iu] = v; P->xrd[iu] = v;
        P->y1[iu] = 0.f; P->y2[iu] = 0.f;
    }
    if (threadIdx.x >= 64 && threadIdx.x < 68) {
        int r = threadIdx.x - 64;
        P->y3[r] = 0.f; P->y4[r] = 0.f;
    }
    xsu = v; xsd = v;
}

// ---------------- main persistent kernel ----------------
__global__ void __launch_bounds__(NT, 1)
opf_kernel(const float* __restrict__ w_scen, const float* __restrict__ Pmax,
           const float* __restrict__ Cost, const float* __restrict__ Cru,
           const float* __restrict__ Crd, const float* __restrict__ PTDF,
           const float* __restrict__ node_G, const float* __restrict__ node_W,
           const float* __restrict__ Pd, const float* __restrict__ w_exp,
           const float* __restrict__ Cap, float* __restrict__ out)
{
    __shared__ __align__(16) float uBuf[cS*cL + cL];   // A: s78t+t (34.8KB) / B: dsh_t
    __shared__ float sdsh[cN];
    __shared__ float psh[cU];
    __shared__ float s78s_sh[cL];
    __shared__ float sA[8*17];
    __shared__ float sB[8*19];
    __shared__ float shp[2], shc[2*cS], sh8[8], sh8b[8];
    __shared__ PState P;

    const int blk  = blockIdx.x;
    const int tid  = blk * NT + threadIdx.x;
    const int wId  = threadIdx.x >> 5;
    const int lane = threadIdx.x & 31;
    const int gw   = blk * 8 + wId;
    float xsu = 0.f, xsd = 0.f;       // n-warp register state
    unsigned rnd;
    {
        unsigned e;
        asm volatile("ld.global.cg.u32 %0, [%1];" : "=r"(e) : "l"(&g_epoch));
        rnd = e;
    }

    // ---- setup 1: index extraction + equality rhs ----
    if (gw < cU) {
        int u = gw, f = -1;
        for (int n = lane; n < cN; n += 32)
            if (node_G[n * cU + u] != 0.f) f = n;
#pragma unroll
        for (int o = 16; o; o >>= 1) f = max(f, __shfl_xor_sync(0xffffffffu, f, o));
        if (lane == 0) __stcg(&g_gidx[u], f);
    } else if (gw < cU + cW) {
        int w = gw - cU, f = -1;
        for (int n = lane; n < cN; n += 32)
            if (node_W[n * cW + w] != 0.f) f = n;
#pragma unroll
        for (int o = 16; o; o >>= 1) f = max(f, __shfl_xor_sync(0xffffffffu, f, o));
        if (lane == 0) __stcg(&g_widx[w], f);
    } else if (gw == cU + cW) {
        float a = 0.f;
        for (int n = lane; n < cN; n += 32) a += Pd[n];
        for (int w = lane; w < cW; w += 32) a -= w_exp[w];
        a = wallred(a);
        if (lane == 0) stcg(&g_beq1, a);
    } else if (gw > cU + cW && gw <= cU + cW + cS) {
        int s = gw - (cU + cW + 1);
        float a = 0.f;
        for (int w = lane; w < cW; w += 32) a += w_scen[s * cW + w];
        a = wallred(a);
        if (lane == 0) stcg(&g_beq2[s], -a);
    }
    gsync(++rnd);

    // ---- setup 2: materialize matrices, rhs, init power-iter state ----
    for (int i = tid; i < cL * cU; i += NTH) {
        int l = i / cU, u = i - l * cU;
        float v = PTDF[l * cN + __ldcg(&g_gidx[u])];
        g_Hg[l * cU + u] = v;
        g_HgT[u * cL + l] = v;
    }
    for (int i = tid; i < cN * cL; i += NTH) {
        int n = i >> 9, l = i & (cL - 1);
        g_PTT[i] = PTDF[l * cN + n];
    }
    if (gw < cL) {
        int l = gw;
        const float* pr = PTDF + l * cN;
        float a = 0.f;
        for (int n = lane; n < cN; n += 32) a -= pr[n] * Pd[n];
        float hw0 = pr[__ldcg(&g_widx[lane])];
        float hw1 = pr[__ldcg(&g_widx[lane + 32])];
        a += hw0 * w_exp[lane] + hw1 * w_exp[lane + 32];
        float cf = wallred(a);
        float cap = Cap[l];
        float c3 = cap - cf, c4 = cap + cf;
        if (lane == 0) { g_c3[l] = c3; g_c4[l] = c4; }
        float bws = 0.f;
#pragma unroll 4
        for (int w = 0; w < 32; w++) {
            float h0 = __shfl_sync(0xffffffffu, hw0, w);
            float h1 = __shfl_sync(0xffffffffu, hw1, w);
            if (lane < cS)
                bws += h0 * w_scen[lane * cW + w] + h1 * w_scen[lane * cW + w + 32];
        }
        if (lane < cS) {
            g_b7[l * cS + lane] = c3 - bws;
            g_b8[l * cS + lane] = c4 + bws;
        }
    }
    // v0 = ones: local state + exchanged arrays + partials
    initP(&P, 1.f, xsu, xsd);
    for (int i = tid; i < cU; i += NTH)    stcg(&g_XBP[i], 1.f);
    for (int i = tid; i < cU*cS; i += NTH) stcg(&g_XBC[i], 0.f);
    for (int i = tid; i < cN; i += NTH)    stcg(&g_XBE[i], 0.f);
    if (tid < NB) {
        stcg(&g_part_ss[tid], (tid == 0) ? 1.f : 0.f);
        stcg(&g_part_e[tid], 0.f);
        stcg(&g_part_p[tid], (tid < 80) ? 2.f : 0.f);
    }
    for (int i = tid; i < 80*cS; i += NTH) stcg(&g_part_c[i], 0.f);
    gsync(++rnd);

    // ---- power iteration for ||A|| (31 fused B/A pairs; norm folded into B) ----
#pragma unroll 1
    for (int it = 0; it <= NPOWER; it++) {
        phaseB<true>(blk, wId, lane, 0.f, PTDF, uBuf, sdsh, psh, sB, &P);
        gsync(++rnd);
        phaseA<true>(blk, wId, lane, 0.f, Cost, Cru, Crd, Pmax,
                     uBuf, sA, shp, shc, sh8, sh8b, s78s_sh, &P, xsu, xsd);
        gsync(++rnd);
    }

    // ---- reset state + compute tau ----
    initP(&P, 0.f, xsu, xsd);
    for (int i = tid; i < cU; i += NTH)    stcg(&g_XBP[i], 0.f);
    for (int i = tid; i < cU*cS; i += NTH) stcg(&g_XBC[i], 0.f);
    for (int i = tid; i < cN; i += NTH)    stcg(&g_XBE[i], 0.f);
    for (int i = tid; i < cL * cS; i += NTH) stcg(&g_s78[i], 0.f);
    for (int i = tid; i < cL; i += NTH) { stcg(&g_s78s[i], 0.f); stcg(&g_t[i], 0.f); }
    if (tid == 0) {
        float a = 0.f;
        for (int b = 0; b < NB; b++) a += ldcg(&g_part_ss[b]);
        float Lop = sqrtf(sqrtf(a));
        stcg(&g_tau, 0.9f / Lop);
        stcg(&g_z1, 0.f); stcg(&g_z2sum, 0.f);
    }
    if (tid < cS) stcg(&g_z2[tid], 0.f);
    gsync(++rnd);

    const float tau = ldcg(&g_tau);

    // ---- PDHG main loop (skip output-irrelevant final phase B) ----
#pragma unroll 1
    for (int it = 0; it < NITERS-1; it++) {
        phaseA<false>(blk, wId, lane, tau, Cost, Cru, Crd, Pmax,
                      uBuf, sA, shp, shc, sh8, sh8b, s78s_sh, &P, xsu, xsd);
        gsync(++rnd);
        phaseB<false>(blk, wId, lane, tau, PTDF, uBuf, sdsh, psh, sB, &P);
        gsync(++rnd);
    }
    phaseA<false>(blk, wId, lane, tau, Cost, Cru, Crd, Pmax,
                  uBuf, sA, shp, shc, sh8, sh8b, s78s_sh, &P, xsu, xsd);
    gsync(++rnd);

    // ---- writeback owned x to global ----
    if (blk < 80) {
        if ((wId & 3) == 0) {
            const int iu = wId >> 2;
            const int u  = 2*blk + iu;
            if (lane == 0) {
                stcg(&g_X[OX_P + u],  P.xp[iu]);
                stcg(&g_X[OX_RU + u], P.xru[iu]);
                stcg(&g_X[OX_RD + u], P.xrd[iu]);
            }
            if (lane < cS) {
                stcg(&g_X[OX_PU + u*cS + lane], P.xpu[iu][lane]);
                stcg(&g_X[OX_PD + u*cS + lane], P.xpd[iu][lane]);
            }
        }
    } else {
        const int wn = (blk - 80)*8 + wId;
        if (wn < cN && lane == 0) {
            stcg(&g_X[OX_SU + wn], xsu);
            stcg(&g_X[OX_SD + wn], xsd);
        }
    }
    gsync(++rnd);

    // ---- output ----
    if (blk < 128 && wId < 4) {
        int l = blk*4 + wId;
        const float* hr = g_Hg + (size_t)l * cU;
        float a = 0.f;
        for (int u = lane; u < cU; u += 32) a = fmaf(hr[u], ldcg(&g_X[OX_P + u]), a);
        a = wallred(a);
        if (lane == 0) {
            out[5600 + l] = g_c3[l] - a;   // f_up = Cap - flow
            out[6112 + l] = g_c4[l] + a;   // f_down = Cap + flow
        }
    } else if ((blk < 128 && wId == 4) || (blk < 32 && wId == 5)) {
        int u = (wId == 4) ? blk : (128 + blk);
        if (lane == 0) {
            out[u]       = ldcg(&g_X[OX_P + u]);
            out[160 + u] = ldcg(&g_X[OX_RU + u]);
            out[320 + u] = ldcg(&g_X[OX_RD + u]);
        }
        if (lane < cS) {
            out[480 + u*cS + lane]  = ldcg(&g_X[OX_PU + u*cS + lane]);
            out[3040 + u*cS + lane] = ldcg(&g_X[OX_PD + u*cS + lane]);
        }
    } else if (blk == 131 && wId == 7) {
        float a = 0.f;
        for (int i = lane; i < cU; i += 32)
            a += Cost[i] * ldcg(&g_X[OX_P + i]) + Cru[i] * ldcg(&g_X[OX_RU + i])
               + Crd[i] * ldcg(&g_X[OX_RD + i]);
        for (int i = lane; i < cN; i += 32)
            a += CVIOL * (ldcg(&g_X[OX_SU + i]) + ldcg(&g_X[OX_SD + i]));
        a = wallred(a);
        if (lane == 0) out[6624] = a;
    }

    // persist the barrier epoch for the next (stream-ordered) launch
    if (blk == 0 && threadIdx.x == 0) {
        asm volatile("st.global.cg.u32 [%0], %1;" :: "l"(&g_epoch), "r"(rnd) : "memory");
    }
}

extern "C" void kernel_launch(void* const* d_in, const int* in_sizes, int n_in,
                              void* d_out, int out_size) {
    const float* w_scen = (const float*)d_in[0];
    const float* Pmax   = (const float*)d_in[1];
    const float* Cost   = (const float*)d_in[2];
    const float* Cru    = (const float*)d_in[3];
    const float* Crd    = (const float*)d_in[4];
    const float* PTDF   = (const float*)d_in[5];
    const float* node_G = (const float*)d_in[6];
    const float* node_W = (const float*)d_in[7];
    // d_in[8] = node_L (identity, unused)
    const float* Pd     = (const float*)d_in[9];
    const float* w_exp  = (const float*)d_in[10];
    const float* Cap    = (const float*)d_in[11];
    float* out = (float*)d_out;
    (void)in_sizes; (void)n_in; (void)out_size;

    opf_kernel<<<NB, NT>>>(w_scen, Pmax, Cost, Cru, Crd, PTDF,
                           node_G, node_W, Pd, w_exp, Cap, out);
}

// round 15
// speedup vs baseline: 1.3095x; 1.0279x over previous
#include <cuda_runtime.h>
#include <math.h>

// ---------------- problem constants ----------------
#define cU 160
#define cL 512
#define cN 400
#define cS 16
#define cW 64
#define CVIOL 20000.0f
#define NITERS 500
#define NPOWER 30

// ---------------- grid constants ----------------
#define NB 132
#define NT 256
#define NTH (NB*NT)

// ---------------- global X layout (output staging only) ----------------
#define OX_P   0
#define OX_RU  160
#define OX_RD  320
#define OX_PU  480
#define OX_PD  3040
#define OX_SU  5600
#define OX_SD  6000
#define XTOT   6400

// ---------------- device state (mutable: ALWAYS accessed via .cg) ----------------
__device__ __align__(16) float g_X[XTOT];        // final output staging only
__device__ __align__(16) float g_XBP[cU];        // exchanged: xbar p (or v.p)
__device__ __align__(16) float g_XBC[cU*cS];     // exchanged: xbar (pu-pd)
__device__ __align__(16) float g_XBE[cN];        // exchanged: xbar (su-sd)
__device__ __align__(16) float g_s78[cL*cS];     // exchanged: y7-y8
__device__ float g_s78s[cL];
__device__ float g_t[cL];
__device__ float g_z1, g_z2[cS], g_z2sum, g_tau;
__device__ float g_part_p[NB], g_part_e[NB], g_part_c[80*cS], g_part_ss[NB];

// immutable after setup (normal loads -> L1-cached)
__device__ float g_Hg[cL*cU];
__device__ float g_HgT[cU*cL];
__device__ float g_PTT[cN*cL];
__device__ float g_c3[cL], g_c4[cL];
__device__ __align__(16) float g_b7[cL*cS];
__device__ __align__(16) float g_b8[cL*cS];
__device__ int   g_gidx[cU];
__device__ int   g_widx[cW];
__device__ float g_beq1, g_beq2[cS];

// ---------------- barrier state ----------------
__device__ unsigned g_arrive[NB*8];
__device__ unsigned g_epoch = 0;

// ---------------- cg helpers ----------------
__device__ __forceinline__ float  ldcg (const float*  p){ return __ldcg(p); }
__device__ __forceinline__ float4 ldcg4(const float4* p){ return __ldcg(p); }
__device__ __forceinline__ void   stcg (float* p, float v){ __stcg(p, v); }

// ---------------- flat-arrival grid barrier ----------------
__device__ __forceinline__ void gsync(unsigned rnd) {
    __syncthreads();
    if (threadIdx.x < 32) {
        const int lane = threadIdx.x;
        if (lane == 0) {
            asm volatile("st.release.gpu.global.u32 [%0], %1;"
                         :: "l"(&g_arrive[blockIdx.x * 8]), "r"(rnd) : "memory");
        }
        const unsigned* p0 = &g_arrive[(lane)              * 8];
        const unsigned* p1 = &g_arrive[(lane + 32)         * 8];
        const unsigned* p2 = &g_arrive[(lane + 64)         * 8];
        const unsigned* p3 = &g_arrive[(lane + 96)         * 8];
        const unsigned* p4 = &g_arrive[(128 + (lane & 3))  * 8];
        for (;;) {
            unsigned a, b, c, d, e;
            asm volatile("ld.acquire.gpu.global.u32 %0, [%1];" : "=r"(a) : "l"(p0) : "memory");
            asm volatile("ld.acquire.gpu.global.u32 %0, [%1];" : "=r"(b) : "l"(p1) : "memory");
            asm volatile("ld.acquire.gpu.global.u32 %0, [%1];" : "=r"(c) : "l"(p2) : "memory");
            asm volatile("ld.acquire.gpu.global.u32 %0, [%1];" : "=r"(d) : "l"(p3) : "memory");
            asm volatile("ld.acquire.gpu.global.u32 %0, [%1];" : "=r"(e) : "l"(p4) : "memory");
            bool ok = ((int)(a - rnd) >= 0) && ((int)(b - rnd) >= 0) &&
                      ((int)(c - rnd) >= 0) && ((int)(d - rnd) >= 0) &&
                      ((int)(e - rnd) >= 0);
            if (__all_sync(0xffffffffu, ok)) break;
            __nanosleep(40);
        }
    }
    __syncthreads();
}

// ---------------- warp helpers ----------------
__device__ __forceinline__ float wallred(float v) {
#pragma unroll
    for (int o = 16; o; o >>= 1) v += __shfl_xor_sync(0xffffffffu, v, o);
    return v;
}

__device__ __forceinline__ void allred16(float (&v)[16]) {
#pragma unroll
    for (int o = 16; o; o >>= 1) {
#pragma unroll
        for (int k = 0; k < 16; k++) v[k] += __shfl_xor_sync(0xffffffffu, v[k], o);
    }
}

__device__ __forceinline__ float pick16(const float (&a)[16], int s) {
    float r = a[0];
#pragma unroll
    for (int k = 1; k < 16; k++) r = (s == k) ? a[k] : r;
    return r;
}

// 16-col fused FMA reading a s78 row straight from L2 (streams under the FMAs)
__device__ __forceinline__ void fma16cg(float (&acc)[16], float h, const float4* p) {
    float4 a0 = __ldcg(p), a1 = __ldcg(p+1), a2 = __ldcg(p+2), a3 = __ldcg(p+3);
    acc[0]  = fmaf(h, a0.x, acc[0]);  acc[1]  = fmaf(h, a0.y, acc[1]);
    acc[2]  = fmaf(h, a0.z, acc[2]);  acc[3]  = fmaf(h, a0.w, acc[3]);
    acc[4]  = fmaf(h, a1.x, acc[4]);  acc[5]  = fmaf(h, a1.y, acc[5]);
    acc[6]  = fmaf(h, a1.z, acc[6]);  acc[7]  = fmaf(h, a1.w, acc[7]);
    acc[8]  = fmaf(h, a2.x, acc[8]);  acc[9]  = fmaf(h, a2.y, acc[9]);
    acc[10] = fmaf(h, a2.z, acc[10]); acc[11] = fmaf(h, a2.w, acc[11]);
    acc[12] = fmaf(h, a3.x, acc[12]); acc[13] = fmaf(h, a3.y, acc[13]);
    acc[14] = fmaf(h, a3.z, acc[14]); acc[15] = fmaf(h, a3.w, acc[15]);
}

// transposed smem read: buf[k*stride + idx]
__device__ __forceinline__ void fma16sh_t(float (&acc)[16], float h,
                                          const float* base, int stride) {
#pragma unroll
    for (int k = 0; k < 16; k++) acc[k] = fmaf(h, base[k * stride], acc[k]);
}

// ---------------- persistent per-block state (smem) ----------------
struct PState {
    float xp[2], xru[2], xrd[2];
    float xpu[2][cS], xpd[2][cS];
    float y1[2], y2[2];
    float y5[2][cS], y6[2][cS];
    float y3[4], y4[4];
    float y7[4][cS], y8[4][cS];
};

// ---------------- Phase A ----------------
// u-part: blocks 0..79 (2 u/block, 4 warps/u, DIRECT .cg reads of s78/t under FMAs).
// n-part: blocks 80..131 (<=1 row/warp, state in registers xsu/xsd).
template<bool POW>
__device__ __forceinline__ void phaseA(int blk, int wId, int lane, float tau,
                                       const float* __restrict__ Cost,
                                       const float* __restrict__ Cru,
                                       const float* __restrict__ Crd,
                                       const float* __restrict__ Pmax,
                                       float* sA, float* shp, float* shc,
                                       float* sh8, float* sh8b, float* s78s_sh,
                                       PState* P, float& xsu, float& xsd)
{
    const float sig = tau;
    if (blk < 80) {
        // ---- u-dot: warp quad (wId>>2) owns u, segment (wId&3)*128 ----
        const int iu = wId >> 2;
        const int u  = 2*blk + iu;
        const int Lb = (wId & 3) * 128;
        const bool comb = ((wId & 3) == 0);
        // prefetch global scalars before the dot
        float z1 = 0.f, z2s = 0.f;
        if (comb) {
            if (lane < cS) z2s = ldcg(&g_z2[lane]);
            z1 = ldcg(&g_z1);
        }
        float accT = 0.f;
        float acc[16];
#pragma unroll
        for (int k = 0; k < 16; k++) acc[k] = 0.f;
        const float* hr = g_HgT + (size_t)u * cL + Lb;
#pragma unroll
        for (int j = 0; j < 4; j++) {
            int lo = lane + 32*j;
            int l  = Lb + lo;
            float h = hr[lo];                     // L1-resident
            accT = fmaf(h, ldcg(&g_t[l]), accT);
            fma16cg(acc, h, reinterpret_cast<const float4*>(g_s78 + (size_t)l * cS));
        }
        accT = wallred(accT);
        allred16(acc);
        if (lane < 16) sA[wId*17 + lane] = pick16(acc, lane);
        if (lane == 0) sA[wId*17 + 16] = accT;
        __syncthreads();

        // ---- combine + update (warps 0 and 4) ----
        if (comb) {
            const int b0 = (iu*4) * 17;
            float aT = sA[b0+16] + sA[b0+17+16] + sA[b0+34+16] + sA[b0+51+16];
            float aS = 0.f;
            if (lane < 16) aS = sA[b0+lane] + sA[b0+17+lane] + sA[b0+34+lane] + sA[b0+51+lane];
            float y5v = (lane < cS) ? P->y5[iu][lane] : 0.f;
            float y6v = (lane < cS) ? P->y6[iu][lane] : 0.f;
            float sum5 = wallred(y5v);
            float sum6 = wallred(y6v);
            float y1u = P->y1[iu], y2u = P->y2[iu];
            float ssu = 0.f;
            float xb_p = 0.f, xb_ru = 0.f, xb_rd = 0.f;
            if (lane == 0) {
                float gp  = y1u - y2u + aT + z1;
                float gru = y1u - sum5;
                float grd = y2u - sum6;
                if (POW) {
                    P->xp[iu] = gp; P->xru[iu] = gru; P->xrd[iu] = grd;
                    stcg(&g_XBP[u], gp);
                    ssu += gp*gp + gru*gru + grd*grd;
                    shp[iu] = gp;
                } else {
                    float x = P->xp[iu];
                    float xn = fmaxf(x - tau*(Cost[u] + gp), 0.f);
                    xb_p = 2.f*xn - x;
                    P->xp[iu] = xn; stcg(&g_XBP[u], xb_p); shp[iu] = xb_p;
                    x = P->xru[iu]; xn = fmaxf(x - tau*(Cru[u] + gru), 0.f);
                    xb_ru = 2.f*xn - x; P->xru[iu] = xn;
                    x = P->xrd[iu]; xn = fmaxf(x - tau*(Crd[u] + grd), 0.f);
                    xb_rd = 2.f*xn - x; P->xrd[iu] = xn;
                }
            }
            if (!POW) {
                xb_ru = __shfl_sync(0xffffffffu, xb_ru, 0);
                xb_rd = __shfl_sync(0xffffffffu, xb_rd, 0);
            }
            if (lane < cS) {
                float gpu_ = y5v + aS + z2s;
                float gpd_ = y6v - aS - z2s;
                if (POW) {
                    P->xpu[iu][lane] = gpu_; P->xpd[iu][lane] = gpd_;
                    stcg(&g_XBC[u*cS + lane], gpu_ - gpd_);
                    ssu += gpu_*gpu_ + gpd_*gpd_;
                    shc[iu*cS + lane] = gpu_ - gpd_;
                } else {
                    float x = P->xpu[iu][lane]; float xn = fmaxf(x - tau*gpu_, 0.f);
                    float xbu = 2.f*xn - x; P->xpu[iu][lane] = xn;
                    x = P->xpd[iu][lane]; xn = fmaxf(x - tau*gpd_, 0.f);
                    float xbd = 2.f*xn - x; P->xpd[iu][lane] = xn;
                    stcg(&g_XBC[u*cS + lane], xbu - xbd);
                    shc[iu*cS + lane] = xbu - xbd;
                    P->y5[iu][lane] = fmaxf(y5v + sig*(xbu - xb_ru), 0.f);
                    P->y6[iu][lane] = fmaxf(y6v + sig*(xbd - xb_rd), 0.f);
                }
            }
            if (!POW && lane == 0) {
                P->y1[iu] = fmaxf(y1u + sig*(xb_p + xb_ru - Pmax[u]), 0.f);
                P->y2[iu] = fmaxf(y2u + sig*(xb_rd - xb_p), 0.f);
            }
            if (POW) {
                float w = wallred(ssu);
                if (lane == 0) sh8[iu] = w;
            }
        }
        __syncthreads();
        if (wId == 0) {
            if (lane == 0) stcg(&g_part_p[blk], shp[0] + shp[1]);
            if (lane < cS) stcg(&g_part_c[blk*cS + lane], shc[lane] + shc[cS + lane]);
            if (POW && lane == 0) stcg(&g_part_ss[blk], sh8[0] + sh8[1]);
        }
    } else {
        for (int i = threadIdx.x; i < cL; i += NT) s78s_sh[i] = ldcg(&g_s78s[i]);
        __syncthreads();
        const int wn = (blk - 80)*8 + wId;   // 0..415, active < 400
        float agg_e = 0.f, agg_ss = 0.f;
        if (wn < cN) {
            float zs = ldcg(&g_z2sum);
            float a0 = 0.f;
            const float* r0 = g_PTT + (size_t)wn * cL;
#pragma unroll 4
            for (int l = lane; l < cL; l += 32) a0 = fmaf(r0[l], s78s_sh[l], a0);
            a0 = wallred(a0);
            if (lane == 0) {
                float gsu = a0 + zs, gsd = -a0 - zs;
                if (POW) {
                    xsu = gsu; xsd = gsd;
                    stcg(&g_XBE[wn], gsu - gsd);
                    agg_ss = gsu*gsu + gsd*gsd;
                    agg_e  = gsu - gsd;
                } else {
                    float x = xsu; float xn = fmaxf(x - tau*(CVIOL + gsu), 0.f);
                    float xbu = 2.f*xn - x; xsu = xn;
                    x = xsd; xn = fmaxf(x - tau*(CVIOL + gsd), 0.f);
                    float xbd = 2.f*xn - x; xsd = xn;
                    stcg(&g_XBE[wn], xbu - xbd);
                    agg_e = xbu - xbd;
                }
            }
        }
        if (lane == 0) { sh8[wId] = agg_e; sh8b[wId] = agg_ss; }
        __syncthreads();
        if (wId == 0 && lane == 0) {
            float se = 0.f, ss = 0.f;
#pragma unroll
            for (int k = 0; k < 8; k++) { se += sh8[k]; ss += sh8b[k]; }
            stcg(&g_part_e[blk], se);
            if (POW) stcg(&g_part_ss[blk], ss);
        }
    }
}

// ---------------- Phase B ----------------
// l-part: blocks 0..127, 4 l/block, 2 warps/l. Dual state in smem P.
// POW: u-owner blocks (0..79) also refresh their u-y rows; eq-duals: blk 128 warp 7.
template<bool POW>
__device__ __forceinline__ void phaseB(int blk, int wId, int lane, float sig,
                                       const float* __restrict__ PTDF,
                                       float* dsh_t, float* sdsh, float* psh, float* sB,
                                       PState* P)
{
    float inv = 1.f;
    if (POW) {
        float a = ldcg(&g_part_ss[lane]) + ldcg(&g_part_ss[lane + 32])
                + ldcg(&g_part_ss[lane + 64]) + ldcg(&g_part_ss[lane + 96])
                + ((lane < 4) ? ldcg(&g_part_ss[128 + lane]) : 0.f);
        a = wallred(a);
        inv = rsqrtf(a);
    }
    if (blk < 128) {
        for (int c = threadIdx.x; c < (cU*cS/4); c += NT) {
            float4 d = ldcg4(reinterpret_cast<const float4*>(g_XBC) + c);
            int u = c >> 2, s0 = (c & 3) * 4;
            dsh_t[(s0+0)*cU + u] = d.x * inv;
            dsh_t[(s0+1)*cU + u] = d.y * inv;
            dsh_t[(s0+2)*cU + u] = d.z * inv;
            dsh_t[(s0+3)*cU + u] = d.w * inv;
        }
        for (int i = threadIdx.x; i < cN; i += NT) sdsh[i] = ldcg(&g_XBE[i]) * inv;
        for (int i = threadIdx.x; i < cU; i += NT) psh[i] = ldcg(&g_XBP[i]) * inv;
        __syncthreads();

        const int r    = wId >> 1;           // local row 0..3
        const int l    = blk*4 + r;
        const int half = wId & 1;

        float accF = 0.f, accP = 0.f;
        float acc[16];
#pragma unroll
        for (int k = 0; k < 16; k++) acc[k] = 0.f;
        const float* hg = g_Hg + (size_t)l * cU;
        const int u0 = half * 80;
        for (int u = u0 + lane; u < u0 + 80; u += 32) {
            float h = hg[u];
            accF = fmaf(h, psh[u], accF);
            fma16sh_t(acc, h, dsh_t + u, cU);
        }
        const float* pr = PTDF + (size_t)l * cN;
        const int n0 = half * 200;
#pragma unroll 2
        for (int n = n0 + lane; n < n0 + 200; n += 32) accP = fmaf(pr[n], sdsh[n], accP);
        accF = wallred(accF);
        accP = wallred(accP);
        allred16(acc);
        if (lane < 16) sB[wId*19 + lane] = pick16(acc, lane);
        if (lane == 0) { sB[wId*19 + 16] = accF; sB[wId*19 + 17] = accP; }
        __syncthreads();
        if (half == 0) {
            float fp = sB[wId*19 + 16] + sB[(wId+1)*19 + 16];
            float aP = sB[wId*19 + 17] + sB[(wId+1)*19 + 17];
            float aS = (lane < 16) ? (sB[wId*19 + lane] + sB[(wId+1)*19 + lane]) : 0.f;
            float base = fp + aP;
            float y3n, y4n;
            if (POW) { y3n = fp; y4n = -fp; }
            else {
                y3n = fmaxf(P->y3[r] + sig*( fp - g_c3[l]), 0.f);
                y4n = fmaxf(P->y4[r] + sig*(-fp - g_c4[l]), 0.f);
            }
            float s78v = 0.f;
            if (lane < cS) {
                float scen = aS + base;
                float y7n, y8n;
                if (POW) { y7n = scen; y8n = -scen; }
                else {
                    y7n = fmaxf(P->y7[r][lane] + sig*( scen - g_b7[l*cS + lane]), 0.f);
                    y8n = fmaxf(P->y8[r][lane] + sig*(-scen - g_b8[l*cS + lane]), 0.f);
                }
                P->y7[r][lane] = y7n;
                P->y8[r][lane] = y8n;
                s78v = y7n - y8n;
                stcg(&g_s78[l*cS + lane], s78v);
            }
            float s78s = wallred(s78v);
            if (lane == 0) {
                P->y3[r] = y3n;
                P->y4[r] = y4n;
                stcg(&g_s78s[l], s78s);
                stcg(&g_t[l], y3n - y4n + s78s);
            }
        }
    }
    // POW: owner blocks refresh their u-y rows from smem v (scaled)
    if (POW && blk < 80 && (wId & 3) == 0) {
        const int iu = wId >> 2;
        float p  = P->xp[iu]  * inv;
        float ru = P->xru[iu] * inv;
        float rd = P->xrd[iu] * inv;
        if (lane == 0) { P->y1[iu] = p + ru; P->y2[iu] = rd - p; }
        if (lane < cS) {
            P->y5[iu][lane] = P->xpu[iu][lane] * inv - ru;
            P->y6[iu][lane] = P->xpd[iu][lane] * inv - rd;
        }
    }
    // equality duals: block 128 warp 7 (idle in l-work)
    if (blk == 128 && wId == 7) {
        float sp = 0.f;
        for (int b = lane; b < 80; b += 32) sp += ldcg(&g_part_p[b]);
        sp = wallred(sp);
        float se = 0.f;
        for (int b = 80 + lane; b < NB; b += 32) se += ldcg(&g_part_e[b]);
        se = wallred(se);
        int s = lane & 15, h = lane >> 4;
        float sc = 0.f;
#pragma unroll
        for (int b = h*40; b < h*40 + 40; b++) sc += ldcg(&g_part_c[b*cS + s]);
        sc += __shfl_xor_sync(0xffffffffu, sc, 16);
        float ae2 = sc + se;
        float z2n = 0.f;
        if (lane < cS) {
            z2n = POW ? (ae2 * inv) : (ldcg(&g_z2[lane]) + sig*(ae2 - g_beq2[lane]));
            stcg(&g_z2[lane], z2n);
        }
        float zsum = wallred((lane < cS) ? z2n : 0.f);
        if (lane == 0) {
            float z1n = POW ? (sp * inv) : (ldcg(&g_z1) + sig*(sp - g_beq1));
            stcg(&g_z1, z1n);
            stcg(&g_z2sum, zsum);
        }
    }
}

// ---------------- state init helper ----------------
__device__ __forceinline__ void initP(PState* P, float v, float& xsu, float& xsd) {
    if (threadIdx.x < cS) {
        int s = threadIdx.x;
#pragma unroll
        for (int iu = 0; iu < 2; iu++) {
            P->xpu[iu][s] = v; P->xpd[iu][s] = v;
            P->y5[iu][s] = 0.f; P->y6[iu][s] = 0.f;
        }
#pragma unroll
        for (int r = 0; r < 4; r++) { P->y7[r][s] = 0.f; P->y8[r][s] = 0.f; }
    }
    if (threadIdx.x >= 32 && threadIdx.x < 34) {
        int iu = threadIdx.x - 32;
        P->xp[iu] = v; P->xru[iu] = v; P->xrd[iu] = v;
        P->y1[iu] = 0.f; P->y2[iu] = 0.f;
    }
    if (threadIdx.x >= 64 && threadIdx.x < 68) {
        int r = threadIdx.x - 64;
        P->y3[r] = 0.f; P->y4[r] = 0.f;
    }
    xsu = v; xsd = v;
}

// ---------------- main persistent kernel ----------------
__global__ void __launch_bounds__(NT, 1)
opf_kernel(const float* __restrict__ w_scen, const float* __restrict__ Pmax,
           const float* __restrict__ Cost, const float* __restrict__ Cru,
           const float* __restrict__ Crd, const float* __restrict__ PTDF,
           const float* __restrict__ node_G, const float* __restrict__ node_W,
           const float* __restrict__ Pd, const float* __restrict__ w_exp,
           const float* __restrict__ Cap, float* __restrict__ out)
{
    __shared__ __align__(16) float dsh_t[cS*cU];   // 10.2 KB (phase B staging)
    __shared__ float sdsh[cN];
    __shared__ float psh[cU];
    __shared__ float s78s_sh[cL];
    __shared__ float sA[8*17];
    __shared__ float sB[8*19];
    __shared__ float shp[2], shc[2*cS], sh8[8], sh8b[8];
    __shared__ PState P;

    const int blk  = blockIdx.x;
    const int tid  = blk * NT + threadIdx.x;
    const int wId  = threadIdx.x >> 5;
    const int lane = threadIdx.x & 31;
    const int gw   = blk * 8 + wId;
    float xsu = 0.f, xsd = 0.f;       // n-warp register state
    unsigned rnd;
    {
        unsigned e;
        asm volatile("ld.global.cg.u32 %0, [%1];" : "=r"(e) : "l"(&g_epoch));
        rnd = e;
    }

    // ---- setup 1: index extraction + equality rhs ----
    if (gw < cU) {
        int u = gw, f = -1;
        for (int n = lane; n < cN; n += 32)
            if (node_G[n * cU + u] != 0.f) f = n;
#pragma unroll
        for (int o = 16; o; o >>= 1) f = max(f, __shfl_xor_sync(0xffffffffu, f, o));
        if (lane == 0) __stcg(&g_gidx[u], f);
    } else if (gw < cU + cW) {
        int w = gw - cU, f = -1;
        for (int n = lane; n < cN; n += 32)
            if (node_W[n * cW + w] != 0.f) f = n;
#pragma unroll
        for (int o = 16; o; o >>= 1) f = max(f, __shfl_xor_sync(0xffffffffu, f, o));
        if (lane == 0) __stcg(&g_widx[w], f);
    } else if (gw == cU + cW) {
        float a = 0.f;
        for (int n = lane; n < cN; n += 32) a += Pd[n];
        for (int w = lane; w < cW; w += 32) a -= w_exp[w];
        a = wallred(a);
        if (lane == 0) stcg(&g_beq1, a);
    } else if (gw > cU + cW && gw <= cU + cW + cS) {
        int s = gw - (cU + cW + 1);
        float a = 0.f;
        for (int w = lane; w < cW; w += 32) a += w_scen[s * cW + w];
        a = wallred(a);
        if (lane == 0) stcg(&g_beq2[s], -a);
    }
    gsync(++rnd);

    // ---- setup 2: materialize matrices, rhs, init power-iter state ----
    for (int i = tid; i < cL * cU; i += NTH) {
        int l = i / cU, u = i - l * cU;
        float v = PTDF[l * cN + __ldcg(&g_gidx[u])];
        g_Hg[l * cU + u] = v;
        g_HgT[u * cL + l] = v;
    }
    for (int i = tid; i < cN * cL; i += NTH) {
        int n = i >> 9, l = i & (cL - 1);
        g_PTT[i] = PTDF[l * cN + n];
    }
    if (gw < cL) {
        int l = gw;
        const float* pr = PTDF + l * cN;
        float a = 0.f;
        for (int n = lane; n < cN; n += 32) a -= pr[n] * Pd[n];
        float hw0 = pr[__ldcg(&g_widx[lane])];
        float hw1 = pr[__ldcg(&g_widx[lane + 32])];
        a += hw0 * w_exp[lane] + hw1 * w_exp[lane + 32];
        float cf = wallred(a);
        float cap = Cap[l];
        float c3 = cap - cf, c4 = cap + cf;
        if (lane == 0) { g_c3[l] = c3; g_c4[l] = c4; }
        float bws = 0.f;
#pragma unroll 4
        for (int w = 0; w < 32; w++) {
            float h0 = __shfl_sync(0xffffffffu, hw0, w);
            float h1 = __shfl_sync(0xffffffffu, hw1, w);
            if (lane < cS)
                bws += h0 * w_scen[lane * cW + w] + h1 * w_scen[lane * cW + w + 32];
        }
        if (lane < cS) {
            g_b7[l * cS + lane] = c3 - bws;
            g_b8[l * cS + lane] = c4 + bws;
        }
    }
    // v0 = ones: local state + exchanged arrays + partials
    initP(&P, 1.f, xsu, xsd);
    for (int i = tid; i < cU; i += NTH)    stcg(&g_XBP[i], 1.f);
    for (int i = tid; i < cU*cS; i += NTH) stcg(&g_XBC[i], 0.f);
    for (int i = tid; i < cN; i += NTH)    stcg(&g_XBE[i], 0.f);
    if (tid < NB) {
        stcg(&g_part_ss[tid], (tid == 0) ? 1.f : 0.f);
        stcg(&g_part_e[tid], 0.f);
        stcg(&g_part_p[tid], (tid < 80) ? 2.f : 0.f);
    }
    for (int i = tid; i < 80*cS; i += NTH) stcg(&g_part_c[i], 0.f);
    gsync(++rnd);

    // ---- power iteration for ||A|| (31 fused B/A pairs; norm folded into B) ----
#pragma unroll 1
    for (int it = 0; it <= NPOWER; it++) {
        phaseB<true>(blk, wId, lane, 0.f, PTDF, dsh_t, sdsh, psh, sB, &P);
        gsync(++rnd);
        phaseA<true>(blk, wId, lane, 0.f, Cost, Cru, Crd, Pmax,
                     sA, shp, shc, sh8, sh8b, s78s_sh, &P, xsu, xsd);
        gsync(++rnd);
    }

    // ---- reset state + compute tau ----
    initP(&P, 0.f, xsu, xsd);
    for (int i = tid; i < cU; i += NTH)    stcg(&g_XBP[i], 0.f);
    for (int i = tid; i < cU*cS; i += NTH) stcg(&g_XBC[i], 0.f);
    for (int i = tid; i < cN; i += NTH)    stcg(&g_XBE[i], 0.f);
    for (int i = tid; i < cL * cS; i += NTH) stcg(&g_s78[i], 0.f);
    for (int i = tid; i < cL; i += NTH) { stcg(&g_s78s[i], 0.f); stcg(&g_t[i], 0.f); }
    if (tid == 0) {
        float a = 0.f;
        for (int b = 0; b < NB; b++) a += ldcg(&g_part_ss[b]);
        float Lop = sqrtf(sqrtf(a));
        stcg(&g_tau, 0.9f / Lop);
        stcg(&g_z1, 0.f); stcg(&g_z2sum, 0.f);
    }
    if (tid < cS) stcg(&g_z2[tid], 0.f);
    gsync(++rnd);

    const float tau = ldcg(&g_tau);

    // ---- PDHG main loop (skip output-irrelevant final phase B) ----
#pragma unroll 1
    for (int it = 0; it < NITERS-1; it++) {
        phaseA<false>(blk, wId, lane, tau, Cost, Cru, Crd, Pmax,
                      sA, shp, shc, sh8, sh8b, s78s_sh, &P, xsu, xsd);
        gsync(++rnd);
        phaseB<false>(blk, wId, lane, tau, PTDF, dsh_t, sdsh, psh, sB, &P);
        gsync(++rnd);
    }
    phaseA<false>(blk, wId, lane, tau, Cost, Cru, Crd, Pmax,
                  sA, shp, shc, sh8, sh8b, s78s_sh, &P, xsu, xsd);
    gsync(++rnd);

    // ---- writeback owned x to global ----
    if (blk < 80) {
        if ((wId & 3) == 0) {
            const int iu = wId >> 2;
            const int u  = 2*blk + iu;
            if (lane == 0) {
                stcg(&g_X[OX_P + u],  P.xp[iu]);
                stcg(&g_X[OX_RU + u], P.xru[iu]);
                stcg(&g_X[OX_RD + u], P.xrd[iu]);
            }
            if (lane < cS) {
                stcg(&g_X[OX_PU + u*cS + lane], P.xpu[iu][lane]);
                stcg(&g_X[OX_PD + u*cS + lane], P.xpd[iu][lane]);
            }
        }
    } else {
        const int wn = (blk - 80)*8 + wId;
        if (wn < cN && lane == 0) {
            stcg(&g_X[OX_SU + wn], xsu);
            stcg(&g_X[OX_SD + wn], xsd);
        }
    }
    gsync(++rnd);

    // ---- output ----
    if (blk < 128 && wId < 4) {
        int l = blk*4 + wId;
        const float* hr = g_Hg + (size_t)l * cU;
        float a = 0.f;
        for (int u = lane; u < cU; u += 32) a = fmaf(hr[u], ldcg(&g_X[OX_P + u]), a);
        a = wallred(a);
        if (lane == 0) {
            out[5600 + l] = g_c3[l] - a;   // f_up = Cap - flow
            out[6112 + l] = g_c4[l] + a;   // f_down = Cap + flow
        }
    } else if ((blk < 128 && wId == 4) || (blk < 32 && wId == 5)) {
        int u = (wId == 4) ? blk : (128 + blk);
        if (lane == 0) {
            out[u]       = ldcg(&g_X[OX_P + u]);
            out[160 + u] = ldcg(&g_X[OX_RU + u]);
            out[320 + u] = ldcg(&g_X[OX_RD + u]);
        }
        if (lane < cS) {
            out[480 + u*cS + lane]  = ldcg(&g_X[OX_PU + u*cS + lane]);
            out[3040 + u*cS + lane] = ldcg(&g_X[OX_PD + u*cS + lane]);
        }
    } else if (blk == 131 && wId == 7) {
        float a = 0.f;
        for (int i = lane; i < cU; i += 32)
            a += Cost[i] * ldcg(&g_X[OX_P + i]) + Cru[i] * ldcg(&g_X[OX_RU + i])
               + Crd[i] * ldcg(&g_X[OX_RD + i]);
        for (int i = lane; i < cN; i += 32)
            a += CVIOL * (ldcg(&g_X[OX_SU + i]) + ldcg(&g_X[OX_SD + i]));
        a = wallred(a);
        if (lane == 0) out[6624] = a;
    }

    // persist the barrier epoch for the next (stream-ordered) launch
    if (blk == 0 && threadIdx.x == 0) {
        asm volatile("st.global.cg.u32 [%0], %1;" :: "l"(&g_epoch), "r"(rnd) : "memory");
    }
}

extern "C" void kernel_launch(void* const* d_in, const int* in_sizes, int n_in,
                              void* d_out, int out_size) {
    const float* w_scen = (const float*)d_in[0];
    const float* Pmax   = (const float*)d_in[1];
    const float* Cost   = (const float*)d_in[2];
    const float* Cru    = (const float*)d_in[3];
    const float* Crd    = (const float*)d_in[4];
    const float* PTDF   = (const float*)d_in[5];
    const float* node_G = (const float*)d_in[6];
    const float* node_W = (const float*)d_in[7];
    // d_in[8] = node_L (identity, unused)
    const float* Pd     = (const float*)d_in[9];
    const float* w_exp  = (const float*)d_in[10];
    const float* Cap    = (const float*)d_in[11];
    float* out = (float*)d_out;
    (void)in_sizes; (void)n_in; (void)out_size;

    opf_kernel<<<NB, NT>>>(w_scen, Pmax, Cost, Cru, Crd, PTDF,
                           node_G, node_W, Pd, w_exp, Cap, out);
}

// round 16
// speedup vs baseline: 1.4265x; 1.0893x over previous
#include <cuda_runtime.h>
#include <math.h>

// ---------------- problem constants ----------------
#define cU 160
#define cL 512
#define cN 400
#define cS 16
#define cW 64
#define CVIOL 20000.0f
#define NITERS 500
#define NPOWER 30

// ---------------- grid constants ----------------
#define NB 132
#define NT 512
#define NTH (NB*NT)

// ---------------- X (primal) layout ----------------
#define OX_P   0
#define OX_RU  160
#define OX_RD  320
#define OX_PU  480
#define OX_PD  3040
#define OX_SU  5600
#define OX_SD  6000
#define XTOT   6400

// ---------------- Y (dual ineq) layout ----------------
#define OY1 0
#define OY2 160
#define OY3 320
#define OY4 832
#define OY5 1344
#define OY6 3904
#define OY7 6464
#define OY8 14656
#define YTOT 22848

// ---------------- device state (mutable: ALWAYS accessed via .cg) ----------------
__device__ __align__(16) float g_X[XTOT];
__device__ __align__(16) float g_XBP[cU];        // exchanged: xbar p
__device__ __align__(16) float g_XBC[cU*cS];     // exchanged: xbar (pu - pd)
__device__ __align__(16) float g_XBE[cN];        // exchanged: xbar (su - sd)
__device__ __align__(16) float g_Y[YTOT];
__device__ __align__(16) float g_s78[cL*cS];
__device__ float g_s78s[cL];
__device__ float g_t[cL];
__device__ float g_z1, g_z2[cS], g_z2sum, g_tau;
__device__ float g_part_p[NB], g_part_e[NB], g_part_c[80*cS], g_part_ss[NB];

// immutable after setup (normal loads -> L1-cached)
__device__ float g_Hg[cL*cU];
__device__ float g_HgT[cU*cL];
__device__ float g_PTT[cN*cL];
__device__ float g_c3[cL], g_c4[cL];
__device__ __align__(16) float g_b7[cL*cS];
__device__ __align__(16) float g_b8[cL*cS];
__device__ int   g_gidx[cU];
__device__ int   g_widx[cW];
__device__ float g_beq1, g_beq2[cS];

// ---------------- barrier state ----------------
__device__ unsigned g_arrive[NB*8];
__device__ unsigned g_epoch = 0;

// ---------------- cg helpers ----------------
__device__ __forceinline__ float  ldcg (const float*  p){ return __ldcg(p); }
__device__ __forceinline__ float4 ldcg4(const float4* p){ return __ldcg(p); }
__device__ __forceinline__ void   stcg (float* p, float v){ __stcg(p, v); }

// ---------------- flat-arrival grid barrier ----------------
__device__ __forceinline__ void gsync(unsigned rnd) {
    __syncthreads();
    if (threadIdx.x < 32) {
        const int lane = threadIdx.x;
        if (lane == 0) {
            asm volatile("st.release.gpu.global.u32 [%0], %1;"
                         :: "l"(&g_arrive[blockIdx.x * 8]), "r"(rnd) : "memory");
        }
        const unsigned* p0 = &g_arrive[(lane)              * 8];
        const unsigned* p1 = &g_arrive[(lane + 32)         * 8];
        const unsigned* p2 = &g_arrive[(lane + 64)         * 8];
        const unsigned* p3 = &g_arrive[(lane + 96)         * 8];
        const unsigned* p4 = &g_arrive[(128 + (lane & 3))  * 8];
        for (;;) {
            unsigned a, b, c, d, e;
            asm volatile("ld.acquire.gpu.global.u32 %0, [%1];" : "=r"(a) : "l"(p0) : "memory");
            asm volatile("ld.acquire.gpu.global.u32 %0, [%1];" : "=r"(b) : "l"(p1) : "memory");
            asm volatile("ld.acquire.gpu.global.u32 %0, [%1];" : "=r"(c) : "l"(p2) : "memory");
            asm volatile("ld.acquire.gpu.global.u32 %0, [%1];" : "=r"(d) : "l"(p3) : "memory");
            asm volatile("ld.acquire.gpu.global.u32 %0, [%1];" : "=r"(e) : "l"(p4) : "memory");
            bool ok = ((int)(a - rnd) >= 0) && ((int)(b - rnd) >= 0) &&
                      ((int)(c - rnd) >= 0) && ((int)(d - rnd) >= 0) &&
                      ((int)(e - rnd) >= 0);
            if (__all_sync(0xffffffffu, ok)) break;
            __nanosleep(40);
        }
    }
    __syncthreads();
}

// ---------------- warp helpers ----------------
__device__ __forceinline__ float wallred(float v) {
#pragma unroll
    for (int o = 16; o; o >>= 1) v += __shfl_xor_sync(0xffffffffu, v, o);
    return v;
}

__device__ __forceinline__ void allred16(float (&v)[16]) {
#pragma unroll
    for (int o = 16; o; o >>= 1) {
#pragma unroll
        for (int k = 0; k < 16; k++) v[k] += __shfl_xor_sync(0xffffffffu, v[k], o);
    }
}

__device__ __forceinline__ float pick16(const float (&a)[16], int s) {
    float r = a[0];
#pragma unroll
    for (int k = 1; k < 16; k++) r = (s == k) ? a[k] : r;
    return r;
}

// dual-u fused 16-col FMA: one s78 row feeds two u accumulator sets
__device__ __forceinline__ void fma16dual(float (&A)[16], float (&B)[16],
                                          float h0, float h1, const float4* p) {
    float4 a0 = __ldcg(p), a1 = __ldcg(p+1), a2 = __ldcg(p+2), a3 = __ldcg(p+3);
    A[0]=fmaf(h0,a0.x,A[0]);   B[0]=fmaf(h1,a0.x,B[0]);
    A[1]=fmaf(h0,a0.y,A[1]);   B[1]=fmaf(h1,a0.y,B[1]);
    A[2]=fmaf(h0,a0.z,A[2]);   B[2]=fmaf(h1,a0.z,B[2]);
    A[3]=fmaf(h0,a0.w,A[3]);   B[3]=fmaf(h1,a0.w,B[3]);
    A[4]=fmaf(h0,a1.x,A[4]);   B[4]=fmaf(h1,a1.x,B[4]);
    A[5]=fmaf(h0,a1.y,A[5]);   B[5]=fmaf(h1,a1.y,B[5]);
    A[6]=fmaf(h0,a1.z,A[6]);   B[6]=fmaf(h1,a1.z,B[6]);
    A[7]=fmaf(h0,a1.w,A[7]);   B[7]=fmaf(h1,a1.w,B[7]);
    A[8]=fmaf(h0,a2.x,A[8]);   B[8]=fmaf(h1,a2.x,B[8]);
    A[9]=fmaf(h0,a2.y,A[9]);   B[9]=fmaf(h1,a2.y,B[9]);
    A[10]=fmaf(h0,a2.z,A[10]); B[10]=fmaf(h1,a2.z,B[10]);
    A[11]=fmaf(h0,a2.w,A[11]); B[11]=fmaf(h1,a2.w,B[11]);
    A[12]=fmaf(h0,a3.x,A[12]); B[12]=fmaf(h1,a3.x,B[12]);
    A[13]=fmaf(h0,a3.y,A[13]); B[13]=fmaf(h1,a3.y,B[13]);
    A[14]=fmaf(h0,a3.z,A[14]); B[14]=fmaf(h1,a3.z,B[14]);
    A[15]=fmaf(h0,a3.w,A[15]); B[15]=fmaf(h1,a3.w,B[15]);
}

// transposed smem read: buf[k*stride + idx]
__device__ __forceinline__ void fma16sh_t(float (&acc)[16], float h,
                                          const float* base, int stride) {
#pragma unroll
    for (int k = 0; k < 16; k++) acc[k] = fmaf(h, base[k * stride], acc[k]);
}

// ---------------- Phase A ----------------
// u-part: blocks 0..79, 2 u/block, 16 warps share ONE pass over s78 (32 rows/warp).
// n-part: blocks 80..131, 2 warps per n-row (256-wide half-dots).
template<bool POW>
__device__ __forceinline__ void phaseA(int blk, int wId, int lane, float tau,
                                       const float* __restrict__ Cost,
                                       const float* __restrict__ Cru,
                                       const float* __restrict__ Crd,
                                       const float* __restrict__ Pmax,
                                       float* sA, float* shn, float* shp, float* shc,
                                       float* sh8, float* sh8b, float* s78s_sh)
{
    const float sig = tau;
    if (blk < 80) {
        const int u0 = 2*blk;
        const bool comb = (wId == 0) || (wId == 8);
        const int iu = wId >> 3;
        const int cu = u0 + iu;
        // prefetch duals on combine warps (hidden under the dot)
        float y5v = 0.f, y6v = 0.f, y1u = 0.f, y2u = 0.f, z1 = 0.f, z2s = 0.f;
        if (comb) {
            if (lane < cS) {
                y5v = ldcg(&g_Y[OY5 + cu*cS + lane]);
                y6v = ldcg(&g_Y[OY6 + cu*cS + lane]);
                z2s = ldcg(&g_z2[lane]);
            }
            y1u = ldcg(&g_Y[OY1 + cu]); y2u = ldcg(&g_Y[OY2 + cu]);
            z1  = ldcg(&g_z1);
        }
        // ---- shared single pass over s78/t: 32 rows per warp, dual-u accumulate ----
        const int l = wId*32 + lane;
        float h0 = g_HgT[(size_t)u0 * cL + l];          // L1-resident
        float h1 = g_HgT[(size_t)(u0+1) * cL + l];
        float tv = ldcg(&g_t[l]);
        float t0 = h0 * tv, t1 = h1 * tv;
        float acc0[16], acc1[16];
#pragma unroll
        for (int k = 0; k < 16; k++) { acc0[k] = 0.f; acc1[k] = 0.f; }
        fma16dual(acc0, acc1, h0, h1,
                  reinterpret_cast<const float4*>(g_s78 + (size_t)l * cS));
        allred16(acc0); allred16(acc1);
        t0 = wallred(t0); t1 = wallred(t1);
        if (lane < 16) {
            sA[wId*34 + lane]      = pick16(acc0, lane);
            sA[wId*34 + 17 + lane] = pick16(acc1, lane);
        }
        if (lane == 0) { sA[wId*34 + 16] = t0; sA[wId*34 + 33] = t1; }
        __syncthreads();

        // ---- combine + update (warps 0 and 8) ----
        if (comb) {
            const int off = iu * 17;
            float v = 0.f;
            if (lane < 17) {
#pragma unroll
                for (int k = 0; k < 16; k++) v += sA[k*34 + off + lane];
            }
            float aT = __shfl_sync(0xffffffffu, v, 16);
            float aS = v;   // lanes 0..15
            float sum5 = wallred((lane < cS) ? y5v : 0.f);
            float sum6 = wallred((lane < cS) ? y6v : 0.f);
            float ssu = 0.f;
            float xb_p = 0.f, xb_ru = 0.f, xb_rd = 0.f;
            if (lane == 0) {
                float gp  = y1u - y2u + aT + z1;
                float gru = y1u - sum5;
                float grd = y2u - sum6;
                if (POW) {
                    stcg(&g_X[OX_P + cu], gp); stcg(&g_X[OX_RU + cu], gru); stcg(&g_X[OX_RD + cu], grd);
                    stcg(&g_XBP[cu], gp);
                    ssu += gp*gp + gru*gru + grd*grd;
                    shp[iu] = gp;
                } else {
                    float x = ldcg(&g_X[OX_P + cu]);
                    float xn = fmaxf(x - tau*(Cost[cu] + gp), 0.f);
                    xb_p = 2.f*xn - x;
                    stcg(&g_X[OX_P + cu], xn); stcg(&g_XBP[cu], xb_p); shp[iu] = xb_p;
                    x = ldcg(&g_X[OX_RU + cu]); xn = fmaxf(x - tau*(Cru[cu] + gru), 0.f);
                    xb_ru = 2.f*xn - x; stcg(&g_X[OX_RU + cu], xn);
                    x = ldcg(&g_X[OX_RD + cu]); xn = fmaxf(x - tau*(Crd[cu] + grd), 0.f);
                    xb_rd = 2.f*xn - x; stcg(&g_X[OX_RD + cu], xn);
                }
            }
            if (!POW) {
                xb_ru = __shfl_sync(0xffffffffu, xb_ru, 0);
                xb_rd = __shfl_sync(0xffffffffu, xb_rd, 0);
            }
            if (lane < cS) {
                float gpu_ = y5v + aS + z2s;
                float gpd_ = y6v - aS - z2s;
                int ixu = OX_PU + cu*cS + lane, ixd = OX_PD + cu*cS + lane;
                if (POW) {
                    stcg(&g_X[ixu], gpu_); stcg(&g_X[ixd], gpd_);
                    stcg(&g_XBC[cu*cS + lane], gpu_ - gpd_);
                    ssu += gpu_*gpu_ + gpd_*gpd_;
                    shc[iu*cS + lane] = gpu_ - gpd_;
                } else {
                    float x = ldcg(&g_X[ixu]); float xn = fmaxf(x - tau*gpu_, 0.f);
                    float xbu = 2.f*xn - x; stcg(&g_X[ixu], xn);
                    x = ldcg(&g_X[ixd]); xn = fmaxf(x - tau*gpd_, 0.f);
                    float xbd = 2.f*xn - x; stcg(&g_X[ixd], xn);
                    stcg(&g_XBC[cu*cS + lane], xbu - xbd);
                    shc[iu*cS + lane] = xbu - xbd;
                    float y5n = fmaxf(y5v + sig*(xbu - xb_ru), 0.f);
                    float y6n = fmaxf(y6v + sig*(xbd - xb_rd), 0.f);
                    stcg(&g_Y[OY5 + cu*cS + lane], y5n);
                    stcg(&g_Y[OY6 + cu*cS + lane], y6n);
                }
            }
            if (!POW && lane == 0) {
                float y1n = fmaxf(y1u + sig*(xb_p + xb_ru - Pmax[cu]), 0.f);
                float y2n = fmaxf(y2u + sig*(xb_rd - xb_p), 0.f);
                stcg(&g_Y[OY1 + cu], y1n); stcg(&g_Y[OY2 + cu], y2n);
            }
            if (POW) {
                float w = wallred(ssu);
                if (lane == 0) sh8[iu] = w;
            }
        }
        __syncthreads();
        if (wId == 0) {
            if (lane == 0) stcg(&g_part_p[blk], shp[0] + shp[1]);
            if (lane < cS) stcg(&g_part_c[blk*cS + lane], shc[lane] + shc[cS + lane]);
            if (POW && lane == 0) stcg(&g_part_ss[blk], sh8[0] + sh8[1]);
        }
    } else {
        for (int i = threadIdx.x; i < cL; i += NT) s78s_sh[i] = ldcg(&g_s78s[i]);
        __syncthreads();
        const int wpair = (blk - 80)*8 + (wId >> 1);   // 0..415, active < 400
        const int half  = wId & 1;
        float zs = ldcg(&g_z2sum);
        if (wpair < cN) {
            float a = 0.f;
            const float* r0 = g_PTT + (size_t)wpair * cL + half*256;
            const float* ss = s78s_sh + half*256;
#pragma unroll
            for (int j = 0; j < 8; j++) {
                int l2 = lane + 32*j;
                a = fmaf(r0[l2], ss[l2], a);
            }
            a = wallred(a);
            if (lane == 0) shn[wId] = a;
        }
        __syncthreads();
        if (half == 0) {
            float agg_e = 0.f, agg_ss = 0.f;
            if (wpair < cN && lane == 0) {
                float a0 = shn[wId] + shn[wId + 1];
                float gsu = a0 + zs, gsd = -a0 - zs;
                if (POW) {
                    stcg(&g_X[OX_SU + wpair], gsu); stcg(&g_X[OX_SD + wpair], gsd);
                    stcg(&g_XBE[wpair], gsu - gsd);
                    agg_ss = gsu*gsu + gsd*gsd;
                    agg_e  = gsu - gsd;
                } else {
                    float x = ldcg(&g_X[OX_SU + wpair]); float xn = fmaxf(x - tau*(CVIOL + gsu), 0.f);
                    float xbu = 2.f*xn - x; stcg(&g_X[OX_SU + wpair], xn);
                    x = ldcg(&g_X[OX_SD + wpair]); xn = fmaxf(x - tau*(CVIOL + gsd), 0.f);
                    float xbd = 2.f*xn - x; stcg(&g_X[OX_SD + wpair], xn);
                    stcg(&g_XBE[wpair], xbu - xbd);
                    agg_e = xbu - xbd;
                }
            }
            if (lane == 0) { sh8[wId >> 1] = agg_e; sh8b[wId >> 1] = agg_ss; }
        }
        __syncthreads();
        if (wId == 0 && lane == 0) {
            float se = 0.f, ss2 = 0.f;
#pragma unroll
            for (int k = 0; k < 8; k++) { se += sh8[k]; ss2 += sh8b[k]; }
            stcg(&g_part_e[blk], se);
            if (POW) stcg(&g_part_ss[blk], ss2);
        }
    }
}

// ---------------- Phase B ----------------
// l-part: blocks 0..127, 4 l/block, 4 warps per l (quarter-dots, smem combine).
// POW: blocks 128..131 write u-y rows; eq-duals: blk 128 warp 7.
template<bool POW>
__device__ __forceinline__ void phaseB(int blk, int wId, int lane, float sig,
                                       const float* __restrict__ PTDF,
                                       float* dsh_t, float* sdsh, float* psh, float* sB)
{
    float inv = 1.f;
    if (POW) {
        float a = ldcg(&g_part_ss[lane]) + ldcg(&g_part_ss[lane + 32])
                + ldcg(&g_part_ss[lane + 64]) + ldcg(&g_part_ss[lane + 96])
                + ((lane < 4) ? ldcg(&g_part_ss[128 + lane]) : 0.f);
        a = wallred(a);
        inv = rsqrtf(a);
    }
    if (blk < 128) {
        for (int c = threadIdx.x; c < (cU*cS/4); c += NT) {
            float4 d = ldcg4(reinterpret_cast<const float4*>(g_XBC) + c);
            int u = c >> 2, s0 = (c & 3) * 4;
            dsh_t[(s0+0)*cU + u] = d.x * inv;
            dsh_t[(s0+1)*cU + u] = d.y * inv;
            dsh_t[(s0+2)*cU + u] = d.z * inv;
            dsh_t[(s0+3)*cU + u] = d.w * inv;
        }
        for (int i = threadIdx.x; i < cN; i += NT) sdsh[i] = ldcg(&g_XBE[i]) * inv;
        for (int i = threadIdx.x; i < cU; i += NT) psh[i] = ldcg(&g_XBP[i]) * inv;
        __syncthreads();

        const int r = wId >> 2;           // local row 0..3
        const int l = blk*4 + r;
        const int q = wId & 3;            // quarter

        // prefetch duals on the combining (q==0) warp
        float y3 = 0.f, y4 = 0.f, y7 = 0.f, y8 = 0.f;
        if (!POW && q == 0) {
            y3 = ldcg(&g_Y[OY3 + l]);
            y4 = ldcg(&g_Y[OY4 + l]);
            if (lane < cS) {
                y7 = ldcg(&g_Y[OY7 + l*cS + lane]);
                y8 = ldcg(&g_Y[OY8 + l*cS + lane]);
            }
        }
        float accF = 0.f, accP = 0.f;
        float acc[16];
#pragma unroll
        for (int k = 0; k < 16; k++) acc[k] = 0.f;
        const float* hg = g_Hg + (size_t)l * cU;
        const int u0 = q * 40;
#pragma unroll 2
        for (int u = u0 + lane; u < u0 + 40; u += 32) {
            float h = hg[u];
            accF = fmaf(h, psh[u], accF);
            fma16sh_t(acc, h, dsh_t + u, cU);
        }
        const float* pr = PTDF + (size_t)l * cN;
        const int n0 = q * 100;
#pragma unroll 2
        for (int n = n0 + lane; n < n0 + 100; n += 32) accP = fmaf(pr[n], sdsh[n], accP);
        accF = wallred(accF);
        accP = wallred(accP);
        allred16(acc);
        if (lane < 16) sB[wId*19 + lane] = pick16(acc, lane);
        if (lane == 0) { sB[wId*19 + 16] = accF; sB[wId*19 + 17] = accP; }
        __syncthreads();
        if (q == 0) {
            float fp = sB[wId*19 + 16] + sB[(wId+1)*19 + 16]
                     + sB[(wId+2)*19 + 16] + sB[(wId+3)*19 + 16];
            float aP = sB[wId*19 + 17] + sB[(wId+1)*19 + 17]
                     + sB[(wId+2)*19 + 17] + sB[(wId+3)*19 + 17];
            float aS = 0.f;
            if (lane < 16)
                aS = sB[wId*19 + lane] + sB[(wId+1)*19 + lane]
                   + sB[(wId+2)*19 + lane] + sB[(wId+3)*19 + lane];
            float base = fp + aP;
            float y3n, y4n;
            if (POW) { y3n = fp; y4n = -fp; }
            else {
                y3n = fmaxf(y3 + sig*( fp - g_c3[l]), 0.f);
                y4n = fmaxf(y4 + sig*(-fp - g_c4[l]), 0.f);
            }
            float s78v = 0.f;
            if (lane < cS) {
                float scen = aS + base;
                float y7n, y8n;
                if (POW) { y7n = scen; y8n = -scen; }
                else {
                    y7n = fmaxf(y7 + sig*( scen - g_b7[l*cS + lane]), 0.f);
                    y8n = fmaxf(y8 + sig*(-scen - g_b8[l*cS + lane]), 0.f);
                }
                stcg(&g_Y[OY7 + l*cS + lane], y7n);
                stcg(&g_Y[OY8 + l*cS + lane], y8n);
                s78v = y7n - y8n;
                stcg(&g_s78[l*cS + lane], s78v);
            }
            float s78s = wallred(s78v);
            if (lane == 0) {
                stcg(&g_Y[OY3 + l], y3n);
                stcg(&g_Y[OY4 + l], y4n);
                stcg(&g_s78s[l], s78s);
                stcg(&g_t[l], y3n - y4n + s78s);
            }
        }
    } else {
        if (POW && wId < 8) {
            const int base = (blk - 128)*40 + wId*5;
#pragma unroll
            for (int r = 0; r < 5; r++) {
                const int u = base + r;
                float ru = ldcg(&g_X[OX_RU + u]) * inv;
                float rd = ldcg(&g_X[OX_RD + u]) * inv;
                if (lane == 0) {
                    float p = ldcg(&g_X[OX_P + u]) * inv;
                    stcg(&g_Y[OY1 + u], p + ru);
                    stcg(&g_Y[OY2 + u], rd - p);
                }
                if (lane < cS) {
                    float pu = ldcg(&g_X[OX_PU + u*cS + lane]) * inv;
                    float pd = ldcg(&g_X[OX_PD + u*cS + lane]) * inv;
                    stcg(&g_Y[OY5 + u*cS + lane], pu - ru);
                    stcg(&g_Y[OY6 + u*cS + lane], pd - rd);
                }
            }
        }
        if (blk == 128 && wId == 15) {
            float sp = 0.f;
            for (int b = lane; b < 80; b += 32) sp += ldcg(&g_part_p[b]);
            sp = wallred(sp);
            float se = 0.f;
            for (int b = 80 + lane; b < NB; b += 32) se += ldcg(&g_part_e[b]);
            se = wallred(se);
            int s = lane & 15, h = lane >> 4;
            float sc = 0.f;
#pragma unroll
            for (int b = h*40; b < h*40 + 40; b++) sc += ldcg(&g_part_c[b*cS + s]);
            sc += __shfl_xor_sync(0xffffffffu, sc, 16);
            float ae2 = sc + se;
            float z2n = 0.f;
            if (lane < cS) {
                z2n = POW ? (ae2 * inv) : (ldcg(&g_z2[lane]) + sig*(ae2 - g_beq2[lane]));
                stcg(&g_z2[lane], z2n);
            }
            float zsum = wallred((lane < cS) ? z2n : 0.f);
            if (lane == 0) {
                float z1n = POW ? (sp * inv) : (ldcg(&g_z1) + sig*(sp - g_beq1));
                stcg(&g_z1, z1n);
                stcg(&g_z2sum, zsum);
            }
        }
    }
}

// ---------------- main persistent kernel ----------------
__global__ void __launch_bounds__(NT, 1)
opf_kernel(const float* __restrict__ w_scen, const float* __restrict__ Pmax,
           const float* __restrict__ Cost, const float* __restrict__ Cru,
           const float* __restrict__ Crd, const float* __restrict__ PTDF,
           const float* __restrict__ node_G, const float* __restrict__ node_W,
           const float* __restrict__ Pd, const float* __restrict__ w_exp,
           const float* __restrict__ Cap, float* __restrict__ out)
{
    __shared__ __align__(16) float dsh_t[cS*cU];   // phase B staging (10.2 KB)
    __shared__ float sdsh[cN];
    __shared__ float psh[cU];
    __shared__ float s78s_sh[cL];
    __shared__ float sA[16*34];
    __shared__ float sB[16*19];
    __shared__ float shn[16];
    __shared__ float shp[2], shc[2*cS], sh8[8], sh8b[8];

    const int blk  = blockIdx.x;
    const int tid  = blk * NT + threadIdx.x;
    const int wId  = threadIdx.x >> 5;
    const int lane = threadIdx.x & 31;
    const int gw   = (wId < 8) ? (blk * 8 + wId) : 0x7fffffff;
    unsigned rnd;
    {
        unsigned e;
        asm volatile("ld.global.cg.u32 %0, [%1];" : "=r"(e) : "l"(&g_epoch));
        rnd = e;
    }

    // ---- setup 1: index extraction + equality rhs ----
    if (gw < cU) {
        int u = gw, f = -1;
        for (int n = lane; n < cN; n += 32)
            if (node_G[n * cU + u] != 0.f) f = n;
#pragma unroll
        for (int o = 16; o; o >>= 1) f = max(f, __shfl_xor_sync(0xffffffffu, f, o));
        if (lane == 0) __stcg(&g_gidx[u], f);
    } else if (gw < cU + cW) {
        int w = gw - cU, f = -1;
        for (int n = lane; n < cN; n += 32)
            if (node_W[n * cW + w] != 0.f) f = n;
#pragma unroll
        for (int o = 16; o; o >>= 1) f = max(f, __shfl_xor_sync(0xffffffffu, f, o));
        if (lane == 0) __stcg(&g_widx[w], f);
    } else if (gw == cU + cW) {
        float a = 0.f;
        for (int n = lane; n < cN; n += 32) a += Pd[n];
        for (int w = lane; w < cW; w += 32) a -= w_exp[w];
        a = wallred(a);
        if (lane == 0) stcg(&g_beq1, a);
    } else if (gw > cU + cW && gw <= cU + cW + cS) {
        int s = gw - (cU + cW + 1);
        float a = 0.f;
        for (int w = lane; w < cW; w += 32) a += w_scen[s * cW + w];
        a = wallred(a);
        if (lane == 0) stcg(&g_beq2[s], -a);
    }
    gsync(++rnd);

    // ---- setup 2: materialize matrices, rhs vectors, init power-iter state ----
    for (int i = tid; i < cL * cU; i += NTH) {
        int l = i / cU, u = i - l * cU;
        float v = PTDF[l * cN + __ldcg(&g_gidx[u])];
        g_Hg[l * cU + u] = v;
        g_HgT[u * cL + l] = v;
    }
    for (int i = tid; i < cN * cL; i += NTH) {
        int n = i >> 9, l = i & (cL - 1);
        g_PTT[i] = PTDF[l * cN + n];
    }
    if (gw < cL) {
        int l = gw;
        const float* pr = PTDF + l * cN;
        float a = 0.f;
        for (int n = lane; n < cN; n += 32) a -= pr[n] * Pd[n];
        float hw0 = pr[__ldcg(&g_widx[lane])];
        float hw1 = pr[__ldcg(&g_widx[lane + 32])];
        a += hw0 * w_exp[lane] + hw1 * w_exp[lane + 32];
        float cf = wallred(a);
        float cap = Cap[l];
        float c3 = cap - cf, c4 = cap + cf;
        if (lane == 0) { g_c3[l] = c3; g_c4[l] = c4; }
        float bws = 0.f;
#pragma unroll 4
        for (int w = 0; w < 32; w++) {
            float h0 = __shfl_sync(0xffffffffu, hw0, w);
            float h1 = __shfl_sync(0xffffffffu, hw1, w);
            if (lane < cS)
                bws += h0 * w_scen[lane * cW + w] + h1 * w_scen[lane * cW + w + 32];
        }
        if (lane < cS) {
            g_b7[l * cS + lane] = c3 - bws;
            g_b8[l * cS + lane] = c4 + bws;
        }
    }
    // init v0 = ones + its eq partials
    for (int i = tid; i < XTOT; i += NTH) stcg(&g_X[i], 1.f);
    for (int i = tid; i < cU; i += NTH)    stcg(&g_XBP[i], 1.f);
    for (int i = tid; i < cU*cS; i += NTH) stcg(&g_XBC[i], 0.f);
    for (int i = tid; i < cN; i += NTH)    stcg(&g_XBE[i], 0.f);
    if (tid < NB) {
        stcg(&g_part_ss[tid], (tid == 0) ? 1.f : 0.f);
        stcg(&g_part_e[tid], 0.f);
        stcg(&g_part_p[tid], (tid < 80) ? 2.f : 0.f);
    }
    for (int i = tid; i < 80*cS; i += NTH) stcg(&g_part_c[i], 0.f);
    gsync(++rnd);

    // ---- power iteration for ||A|| (31 fused B/A pairs; norm folded into B) ----
#pragma unroll 1
    for (int it = 0; it <= NPOWER; it++) {
        phaseB<true>(blk, wId, lane, 0.f, PTDF, dsh_t, sdsh, psh, sB);
        gsync(++rnd);
        phaseA<true>(blk, wId, lane, 0.f, Cost, Cru, Crd, Pmax,
                     sA, shn, shp, shc, sh8, sh8b, s78s_sh);
        gsync(++rnd);
    }

    // ---- reset state + compute tau ----
    for (int i = tid; i < XTOT; i += NTH) stcg(&g_X[i], 0.f);
    for (int i = tid; i < cU; i += NTH)    stcg(&g_XBP[i], 0.f);
    for (int i = tid; i < cU*cS; i += NTH) stcg(&g_XBC[i], 0.f);
    for (int i = tid; i < cN; i += NTH)    stcg(&g_XBE[i], 0.f);
    for (int i = tid; i < YTOT; i += NTH) stcg(&g_Y[i], 0.f);
    for (int i = tid; i < cL * cS; i += NTH) stcg(&g_s78[i], 0.f);
    for (int i = tid; i < cL; i += NTH) { stcg(&g_s78s[i], 0.f); stcg(&g_t[i], 0.f); }
    if (tid == 0) {
        float a = 0.f;
        for (int b = 0; b < NB; b++) a += ldcg(&g_part_ss[b]);
        float Lop = sqrtf(sqrtf(a));
        stcg(&g_tau, 0.9f / Lop);
        stcg(&g_z1, 0.f); stcg(&g_z2sum, 0.f);
    }
    if (tid < cS) stcg(&g_z2[tid], 0.f);
    gsync(++rnd);

    const float tau = ldcg(&g_tau);

    // ---- PDHG main loop (skip output-irrelevant final phase B) ----
#pragma unroll 1
    for (int it = 0; it < NITERS-1; it++) {
        phaseA<false>(blk, wId, lane, tau, Cost, Cru, Crd, Pmax,
                      sA, shn, shp, shc, sh8, sh8b, s78s_sh);
        gsync(++rnd);
        phaseB<false>(blk, wId, lane, tau, PTDF, dsh_t, sdsh, psh, sB);
        gsync(++rnd);
    }
    phaseA<false>(blk, wId, lane, tau, Cost, Cru, Crd, Pmax,
                  sA, shn, shp, shc, sh8, sh8b, s78s_sh);
    gsync(++rnd);

    // ---- output ----
    if (blk < 128 && wId < 4) {
        int l = blk*4 + wId;
        const float* hr = g_Hg + (size_t)l * cU;
        float a = 0.f;
        for (int u = lane; u < cU; u += 32) a = fmaf(hr[u], ldcg(&g_X[OX_P + u]), a);
        a = wallred(a);
        if (lane == 0) {
            out[5600 + l] = g_c3[l] - a;   // f_up = Cap - flow
            out[6112 + l] = g_c4[l] + a;   // f_down = Cap + flow
        }
    } else if ((blk < 128 && wId == 4) || (blk < 32 && wId == 5)) {
        int u = (wId == 4) ? blk : (128 + blk);
        if (lane == 0) {
            out[u]       = ldcg(&g_X[OX_P + u]);
            out[160 + u] = ldcg(&g_X[OX_RU + u]);
            out[320 + u] = ldcg(&g_X[OX_RD + u]);
        }
        if (lane < cS) {
            out[480 + u*cS + lane]  = ldcg(&g_X[OX_PU + u*cS + lane]);
            out[3040 + u*cS + lane] = ldcg(&g_X[OX_PD + u*cS + lane]);
        }
    } else if (blk == 131 && wId == 15) {
        float a = 0.f;
        for (int i = lane; i < cU; i += 32)
            a += Cost[i] * ldcg(&g_X[OX_P + i]) + Cru[i] * ldcg(&g_X[OX_RU + i])
               + Crd[i] * ldcg(&g_X[OX_RD + i]);
        for (int i = lane; i < cN; i += 32)
            a += CVIOL * (ldcg(&g_X[OX_SU + i]) + ldcg(&g_X[OX_SD + i]));
        a = wallred(a);
        if (lane == 0) out[6624] = a;
    }

    // persist the barrier epoch for the next (stream-ordered) launch
    if (blk == 0 && threadIdx.x == 0) {
        asm volatile("st.global.cg.u32 [%0], %1;" :: "l"(&g_epoch), "r"(rnd) : "memory");
    }
}

extern "C" void kernel_launch(void* const* d_in, const int* in_sizes, int n_in,
                              void* d_out, int out_size) {
    const float* w_scen = (const float*)d_in[0];
    const float* Pmax   = (const float*)d_in[1];
    const float* Cost   = (const float*)d_in[2];
    const float* Cru    = (const float*)d_in[3];
    const float* Crd    = (const float*)d_in[4];
    const float* PTDF   = (const float*)d_in[5];
    const float* node_G = (const float*)d_in[6];
    const float* node_W = (const float*)d_in[7];
    // d_in[8] = node_L (identity, unused)
    const float* Pd     = (const float*)d_in[9];
    const float* w_exp  = (const float*)d_in[10];
    const float* Cap    = (const float*)d_in[11];
    float* out = (float*)d_out;
    (void)in_sizes; (void)n_in; (void)out_size;

    opf_kernel<<<NB, NT>>>(w_scen, Pmax, Cost, Cru, Crd, PTDF,
                           node_G, node_W, Pd, w_exp, Cap, out);
}

// round 17
// speedup vs baseline: 1.5881x; 1.1133x over previous
#include <cuda_runtime.h>
#include <math.h>

// ---------------- problem constants ----------------
#define cU 160
#define cL 512
#define cN 400
#define cS 16
#define cW 64
#define CVIOL 20000.0f
#define NITERS 500
#define NPOWER 30

// ---------------- grid constants ----------------
#define NB 132
#define NT 512
#define NTH (NB*NT)

// ---------------- X (primal) layout ----------------
#define OX_P   0
#define OX_RU  160
#define OX_RD  320
#define OX_PU  480
#define OX_PD  3040
#define OX_SU  5600
#define OX_SD  6000
#define XTOT   6400

// ---------------- Y (dual ineq) layout ----------------
#define OY1 0
#define OY2 160
#define OY3 320
#define OY4 832
#define OY5 1344
#define OY6 3904
#define OY7 6464
#define OY8 14656
#define YTOT 22848

// ---------------- device state (mutable: ALWAYS accessed via .cg) ----------------
__device__ __align__(16) float g_X[XTOT];
__device__ __align__(16) float g_XBP[cU];        // exchanged: xbar p
__device__ __align__(16) float g_XBC[cU*cS];     // exchanged: xbar (pu - pd)
__device__ __align__(16) float g_XBE[cN];        // exchanged: xbar (su - sd)
__device__ __align__(16) float g_Y[YTOT];
__device__ __align__(16) float g_s78[cL*cS];
__device__ float g_s78s[cL];
__device__ float g_t[cL];
__device__ float g_z1, g_z2[cS], g_z2sum, g_tau;
__device__ float g_part_p[NB], g_part_e[NB], g_part_c[80*cS], g_part_ss[NB];

// immutable after setup (normal loads -> L1-cached)
__device__ float g_Hg[cL*cU];
__device__ float g_HgT[cU*cL];
__device__ float g_PTT[cN*cL];
__device__ float g_c3[cL], g_c4[cL];
__device__ __align__(16) float g_b7[cL*cS];
__device__ __align__(16) float g_b8[cL*cS];
__device__ int   g_gidx[cU];
__device__ int   g_widx[cW];
__device__ float g_beq1, g_beq2[cS];

// ---------------- barrier state ----------------
__device__ unsigned g_arrive[NB*8];
__device__ unsigned g_epoch = 0;

// ---------------- cg helpers ----------------
__device__ __forceinline__ float  ldcg (const float*  p){ return __ldcg(p); }
__device__ __forceinline__ float4 ldcg4(const float4* p){ return __ldcg(p); }
__device__ __forceinline__ void   stcg (float* p, float v){ __stcg(p, v); }

// ---------------- flat-arrival grid barrier (TIGHT SPIN, no sleep) ----------------
__device__ __forceinline__ void gsync(unsigned rnd) {
    __syncthreads();
    if (threadIdx.x < 32) {
        const int lane = threadIdx.x;
        if (lane == 0) {
            asm volatile("st.release.gpu.global.u32 [%0], %1;"
                         :: "l"(&g_arrive[blockIdx.x * 8]), "r"(rnd) : "memory");
        }
        const unsigned* p0 = &g_arrive[(lane)              * 8];
        const unsigned* p1 = &g_arrive[(lane + 32)         * 8];
        const unsigned* p2 = &g_arrive[(lane + 64)         * 8];
        const unsigned* p3 = &g_arrive[(lane + 96)         * 8];
        const unsigned* p4 = &g_arrive[(128 + (lane & 3))  * 8];
        bool ok;
        do {
            unsigned a, b, c, d, e;
            asm volatile("ld.acquire.gpu.global.u32 %0, [%1];" : "=r"(a) : "l"(p0) : "memory");
            asm volatile("ld.acquire.gpu.global.u32 %0, [%1];" : "=r"(b) : "l"(p1) : "memory");
            asm volatile("ld.acquire.gpu.global.u32 %0, [%1];" : "=r"(c) : "l"(p2) : "memory");
            asm volatile("ld.acquire.gpu.global.u32 %0, [%1];" : "=r"(d) : "l"(p3) : "memory");
            asm volatile("ld.acquire.gpu.global.u32 %0, [%1];" : "=r"(e) : "l"(p4) : "memory");
            ok = ((int)(a - rnd) >= 0) && ((int)(b - rnd) >= 0) &&
                 ((int)(c - rnd) >= 0) && ((int)(d - rnd) >= 0) &&
                 ((int)(e - rnd) >= 0);
        } while (!__all_sync(0xffffffffu, ok));
    }
    __syncthreads();
}

// ---------------- warp helpers ----------------
__device__ __forceinline__ float wallred(float v) {
#pragma unroll
    for (int o = 16; o; o >>= 1) v += __shfl_xor_sync(0xffffffffu, v, o);
    return v;
}

__device__ __forceinline__ void allred16(float (&v)[16]) {
#pragma unroll
    for (int o = 16; o; o >>= 1) {
#pragma unroll
        for (int k = 0; k < 16; k++) v[k] += __shfl_xor_sync(0xffffffffu, v[k], o);
    }
}

__device__ __forceinline__ float pick16(const float (&a)[16], int s) {
    float r = a[0];
#pragma unroll
    for (int k = 1; k < 16; k++) r = (s == k) ? a[k] : r;
    return r;
}

// dual-u fused 16-col FMA: one s78 row feeds two u accumulator sets
__device__ __forceinline__ void fma16dual(float (&A)[16], float (&B)[16],
                                          float h0, float h1, const float4* p) {
    float4 a0 = __ldcg(p), a1 = __ldcg(p+1), a2 = __ldcg(p+2), a3 = __ldcg(p+3);
    A[0]=fmaf(h0,a0.x,A[0]);   B[0]=fmaf(h1,a0.x,B[0]);
    A[1]=fmaf(h0,a0.y,A[1]);   B[1]=fmaf(h1,a0.y,B[1]);
    A[2]=fmaf(h0,a0.z,A[2]);   B[2]=fmaf(h1,a0.z,B[2]);
    A[3]=fmaf(h0,a0.w,A[3]);   B[3]=fmaf(h1,a0.w,B[3]);
    A[4]=fmaf(h0,a1.x,A[4]);   B[4]=fmaf(h1,a1.x,B[4]);
    A[5]=fmaf(h0,a1.y,A[5]);   B[5]=fmaf(h1,a1.y,B[5]);
    A[6]=fmaf(h0,a1.z,A[6]);   B[6]=fmaf(h1,a1.z,B[6]);
    A[7]=fmaf(h0,a1.w,A[7]);   B[7]=fmaf(h1,a1.w,B[7]);
    A[8]=fmaf(h0,a2.x,A[8]);   B[8]=fmaf(h1,a2.x,B[8]);
    A[9]=fmaf(h0,a2.y,A[9]);   B[9]=fmaf(h1,a2.y,B[9]);
    A[10]=fmaf(h0,a2.z,A[10]); B[10]=fmaf(h1,a2.z,B[10]);
    A[11]=fmaf(h0,a2.w,A[11]); B[11]=fmaf(h1,a2.w,B[11]);
    A[12]=fmaf(h0,a3.x,A[12]); B[12]=fmaf(h1,a3.x,B[12]);
    A[13]=fmaf(h0,a3.y,A[13]); B[13]=fmaf(h1,a3.y,B[13]);
    A[14]=fmaf(h0,a3.z,A[14]); B[14]=fmaf(h1,a3.z,B[14]);
    A[15]=fmaf(h0,a3.w,A[15]); B[15]=fmaf(h1,a3.w,B[15]);
}

// transposed smem read: buf[k*stride + idx]
__device__ __forceinline__ void fma16sh_t(float (&acc)[16], float h,
                                          const float* base, int stride) {
#pragma unroll
    for (int k = 0; k < 16; k++) acc[k] = fmaf(h, base[k * stride], acc[k]);
}

// ---------------- Phase A ----------------
// u-part: blocks 0..79, 2 u/block, 16 warps share ONE pass over s78 (32 rows/warp).
// n-part: blocks 80..131, 2 warps per n-row (256-wide half-dots).
template<bool POW>
__device__ __forceinline__ void phaseA(int blk, int wId, int lane, float tau,
                                       const float* __restrict__ Cost,
                                       const float* __restrict__ Cru,
                                       const float* __restrict__ Crd,
                                       const float* __restrict__ Pmax,
                                       float* sA, float* shn, float* shp, float* shc,
                                       float* sh8, float* sh8b, float* s78s_sh)
{
    const float sig = tau;
    if (blk < 80) {
        const int u0 = 2*blk;
        const bool comb = (wId == 0) || (wId == 8);
        const int iu = wId >> 3;
        const int cu = u0 + iu;
        // prefetch duals on combine warps (hidden under the dot)
        float y5v = 0.f, y6v = 0.f, y1u = 0.f, y2u = 0.f, z1 = 0.f, z2s = 0.f;
        if (comb) {
            if (lane < cS) {
                y5v = ldcg(&g_Y[OY5 + cu*cS + lane]);
                y6v = ldcg(&g_Y[OY6 + cu*cS + lane]);
                z2s = ldcg(&g_z2[lane]);
            }
            y1u = ldcg(&g_Y[OY1 + cu]); y2u = ldcg(&g_Y[OY2 + cu]);
            z1  = ldcg(&g_z1);
        }
        // ---- shared single pass over s78/t: 32 rows per warp, dual-u accumulate ----
        const int l = wId*32 + lane;
        float h0 = g_HgT[(size_t)u0 * cL + l];          // L1-resident
        float h1 = g_HgT[(size_t)(u0+1) * cL + l];
        float tv = ldcg(&g_t[l]);
        float t0 = h0 * tv, t1 = h1 * tv;
        float acc0[16], acc1[16];
#pragma unroll
        for (int k = 0; k < 16; k++) { acc0[k] = 0.f; acc1[k] = 0.f; }
        fma16dual(acc0, acc1, h0, h1,
                  reinterpret_cast<const float4*>(g_s78 + (size_t)l * cS));
        allred16(acc0); allred16(acc1);
        t0 = wallred(t0); t1 = wallred(t1);
        if (lane < 16) {
            sA[wId*34 + lane]      = pick16(acc0, lane);
            sA[wId*34 + 17 + lane] = pick16(acc1, lane);
        }
        if (lane == 0) { sA[wId*34 + 16] = t0; sA[wId*34 + 33] = t1; }
        __syncthreads();

        // ---- combine + update (warps 0 and 8) ----
        if (comb) {
            const int off = iu * 17;
            float v = 0.f;
            if (lane < 17) {
#pragma unroll
                for (int k = 0; k < 16; k++) v += sA[k*34 + off + lane];
            }
            float aT = __shfl_sync(0xffffffffu, v, 16);
            float aS = v;   // lanes 0..15
            float sum5 = wallred((lane < cS) ? y5v : 0.f);
            float sum6 = wallred((lane < cS) ? y6v : 0.f);
            float ssu = 0.f;
            float xb_p = 0.f, xb_ru = 0.f, xb_rd = 0.f;
            if (lane == 0) {
                float gp  = y1u - y2u + aT + z1;
                float gru = y1u - sum5;
                float grd = y2u - sum6;
                if (POW) {
                    stcg(&g_X[OX_P + cu], gp); stcg(&g_X[OX_RU + cu], gru); stcg(&g_X[OX_RD + cu], grd);
                    stcg(&g_XBP[cu], gp);
                    ssu += gp*gp + gru*gru + grd*grd;
                    shp[iu] = gp;
                } else {
                    float x = ldcg(&g_X[OX_P + cu]);
                    float xn = fmaxf(x - tau*(Cost[cu] + gp), 0.f);
                    xb_p = 2.f*xn - x;
                    stcg(&g_X[OX_P + cu], xn); stcg(&g_XBP[cu], xb_p); shp[iu] = xb_p;
                    x = ldcg(&g_X[OX_RU + cu]); xn = fmaxf(x - tau*(Cru[cu] + gru), 0.f);
                    xb_ru = 2.f*xn - x; stcg(&g_X[OX_RU + cu], xn);
                    x = ldcg(&g_X[OX_RD + cu]); xn = fmaxf(x - tau*(Crd[cu] + grd), 0.f);
                    xb_rd = 2.f*xn - x; stcg(&g_X[OX_RD + cu], xn);
                }
            }
            if (!POW) {
                xb_ru = __shfl_sync(0xffffffffu, xb_ru, 0);
                xb_rd = __shfl_sync(0xffffffffu, xb_rd, 0);
            }
            if (lane < cS) {
                float gpu_ = y5v + aS + z2s;
                float gpd_ = y6v - aS - z2s;
                int ixu = OX_PU + cu*cS + lane, ixd = OX_PD + cu*cS + lane;
                if (POW) {
                    stcg(&g_X[ixu], gpu_); stcg(&g_X[ixd], gpd_);
                    stcg(&g_XBC[cu*cS + lane], gpu_ - gpd_);
                    ssu += gpu_*gpu_ + gpd_*gpd_;
                    shc[iu*cS + lane] = gpu_ - gpd_;
                } else {
                    float x = ldcg(&g_X[ixu]); float xn = fmaxf(x - tau*gpu_, 0.f);
                    float xbu = 2.f*xn - x; stcg(&g_X[ixu], xn);
                    x = ldcg(&g_X[ixd]); xn = fmaxf(x - tau*gpd_, 0.f);
                    float xbd = 2.f*xn - x; stcg(&g_X[ixd], xn);
                    stcg(&g_XBC[cu*cS + lane], xbu - xbd);
                    shc[iu*cS + lane] = xbu - xbd;
                    float y5n = fmaxf(y5v + sig*(xbu - xb_ru), 0.f);
                    float y6n = fmaxf(y6v + sig*(xbd - xb_rd), 0.f);
                    stcg(&g_Y[OY5 + cu*cS + lane], y5n);
                    stcg(&g_Y[OY6 + cu*cS + lane], y6n);
                }
            }
            if (!POW && lane == 0) {
                float y1n = fmaxf(y1u + sig*(xb_p + xb_ru - Pmax[cu]), 0.f);
                float y2n = fmaxf(y2u + sig*(xb_rd - xb_p), 0.f);
                stcg(&g_Y[OY1 + cu], y1n); stcg(&g_Y[OY2 + cu], y2n);
            }
            if (POW) {
                float w = wallred(ssu);
                if (lane == 0) sh8[iu] = w;
            }
        }
        __syncthreads();
        if (wId == 0) {
            if (lane == 0) stcg(&g_part_p[blk], shp[0] + shp[1]);
            if (lane < cS) stcg(&g_part_c[blk*cS + lane], shc[lane] + shc[cS + lane]);
            if (POW && lane == 0) stcg(&g_part_ss[blk], sh8[0] + sh8[1]);
        }
    } else {
        for (int i = threadIdx.x; i < cL; i += NT) s78s_sh[i] = ldcg(&g_s78s[i]);
        __syncthreads();
        const int wpair = (blk - 80)*8 + (wId >> 1);   // 0..415, active < 400
        const int half  = wId & 1;
        float zs = ldcg(&g_z2sum);
        if (wpair < cN) {
            float a = 0.f;
            const float* r0 = g_PTT + (size_t)wpair * cL + half*256;
            const float* ss = s78s_sh + half*256;
#pragma unroll
            for (int j = 0; j < 8; j++) {
                int l2 = lane + 32*j;
                a = fmaf(r0[l2], ss[l2], a);
            }
            a = wallred(a);
            if (lane == 0) shn[wId] = a;
        }
        __syncthreads();
        if (half == 0) {
            float agg_e = 0.f, agg_ss = 0.f;
            if (wpair < cN && lane == 0) {
                float a0 = shn[wId] + shn[wId + 1];
                float gsu = a0 + zs, gsd = -a0 - zs;
                if (POW) {
                    stcg(&g_X[OX_SU + wpair], gsu); stcg(&g_X[OX_SD + wpair], gsd);
                    stcg(&g_XBE[wpair], gsu - gsd);
                    agg_ss = gsu*gsu + gsd*gsd;
                    agg_e  = gsu - gsd;
                } else {
                    float x = ldcg(&g_X[OX_SU + wpair]); float xn = fmaxf(x - tau*(CVIOL + gsu), 0.f);
                    float xbu = 2.f*xn - x; stcg(&g_X[OX_SU + wpair], xn);
                    x = ldcg(&g_X[OX_SD + wpair]); xn = fmaxf(x - tau*(CVIOL + gsd), 0.f);
                    float xbd = 2.f*xn - x; stcg(&g_X[OX_SD + wpair], xn);
                    stcg(&g_XBE[wpair], xbu - xbd);
                    agg_e = xbu - xbd;
                }
            }
            if (lane == 0) { sh8[wId >> 1] = agg_e; sh8b[wId >> 1] = agg_ss; }
        }
        __syncthreads();
        if (wId == 0 && lane == 0) {
            float se = 0.f, ss2 = 0.f;
#pragma unroll
            for (int k = 0; k < 8; k++) { se += sh8[k]; ss2 += sh8b[k]; }
            stcg(&g_part_e[blk], se);
            if (POW) stcg(&g_part_ss[blk], ss2);
        }
    }
}

// ---------------- Phase B ----------------
// l-part: blocks 0..127, 4 l/block, 4 warps per l (quarter-dots, smem combine).
// POW: blocks 128..131 write u-y rows; eq-duals: blk 128 warp 15.
template<bool POW>
__device__ __forceinline__ void phaseB(int blk, int wId, int lane, float sig,
                                       const float* __restrict__ PTDF,
                                       float* dsh_t, float* sdsh, float* psh, float* sB)
{
    float inv = 1.f;
    if (POW) {
        float a = ldcg(&g_part_ss[lane]) + ldcg(&g_part_ss[lane + 32])
                + ldcg(&g_part_ss[lane + 64]) + ldcg(&g_part_ss[lane + 96])
                + ((lane < 4) ? ldcg(&g_part_ss[128 + lane]) : 0.f);
        a = wallred(a);
        inv = rsqrtf(a);
    }
    if (blk < 128) {
        for (int c = threadIdx.x; c < (cU*cS/4); c += NT) {
            float4 d = ldcg4(reinterpret_cast<const float4*>(g_XBC) + c);
            int u = c >> 2, s0 = (c & 3) * 4;
            dsh_t[(s0+0)*cU + u] = d.x * inv;
            dsh_t[(s0+1)*cU + u] = d.y * inv;
            dsh_t[(s0+2)*cU + u] = d.z * inv;
            dsh_t[(s0+3)*cU + u] = d.w * inv;
        }
        for (int i = threadIdx.x; i < cN; i += NT) sdsh[i] = ldcg(&g_XBE[i]) * inv;
        for (int i = threadIdx.x; i < cU; i += NT) psh[i] = ldcg(&g_XBP[i]) * inv;
        __syncthreads();

        const int r = wId >> 2;           // local row 0..3
        const int l = blk*4 + r;
        const int q = wId & 3;            // quarter

        // prefetch duals on the combining (q==0) warp
        float y3 = 0.f, y4 = 0.f, y7 = 0.f, y8 = 0.f;
        if (!POW && q == 0) {
            y3 = ldcg(&g_Y[OY3 + l]);
            y4 = ldcg(&g_Y[OY4 + l]);
            if (lane < cS) {
                y7 = ldcg(&g_Y[OY7 + l*cS + lane]);
                y8 = ldcg(&g_Y[OY8 + l*cS + lane]);
            }
        }
        float accF = 0.f, accP = 0.f;
        float acc[16];
#pragma unroll
        for (int k = 0; k < 16; k++) acc[k] = 0.f;
        const float* hg = g_Hg + (size_t)l * cU;
        const int u0 = q * 40;
#pragma unroll 2
        for (int u = u0 + lane; u < u0 + 40; u += 32) {
            float h = hg[u];
            accF = fmaf(h, psh[u], accF);
            fma16sh_t(acc, h, dsh_t + u, cU);
        }
        const float* pr = PTDF + (size_t)l * cN;
        const int n0 = q * 100;
#pragma unroll 2
        for (int n = n0 + lane; n < n0 + 100; n += 32) accP = fmaf(pr[n], sdsh[n], accP);
        accF = wallred(accF);
        accP = wallred(accP);
        allred16(acc);
        if (lane < 16) sB[wId*19 + lane] = pick16(acc, lane);
        if (lane == 0) { sB[wId*19 + 16] = accF; sB[wId*19 + 17] = accP; }
        __syncthreads();
        if (q == 0) {
            float fp = sB[wId*19 + 16] + sB[(wId+1)*19 + 16]
                     + sB[(wId+2)*19 + 16] + sB[(wId+3)*19 + 16];
            float aP = sB[wId*19 + 17] + sB[(wId+1)*19 + 17]
                     + sB[(wId+2)*19 + 17] + sB[(wId+3)*19 + 17];
            float aS = 0.f;
            if (lane < 16)
                aS = sB[wId*19 + lane] + sB[(wId+1)*19 + lane]
                   + sB[(wId+2)*19 + lane] + sB[(wId+3)*19 + lane];
            float base = fp + aP;
            float y3n, y4n;
            if (POW) { y3n = fp; y4n = -fp; }
            else {
                y3n = fmaxf(y3 + sig*( fp - g_c3[l]), 0.f);
                y4n = fmaxf(y4 + sig*(-fp - g_c4[l]), 0.f);
            }
            float s78v = 0.f;
            if (lane < cS) {
                float scen = aS + base;
                float y7n, y8n;
                if (POW) { y7n = scen; y8n = -scen; }
                else {
                    y7n = fmaxf(y7 + sig*( scen - g_b7[l*cS + lane]), 0.f);
                    y8n = fmaxf(y8 + sig*(-scen - g_b8[l*cS + lane]), 0.f);
                }
                stcg(&g_Y[OY7 + l*cS + lane], y7n);
                stcg(&g_Y[OY8 + l*cS + lane], y8n);
                s78v = y7n - y8n;
                stcg(&g_s78[l*cS + lane], s78v);
            }
            float s78s = wallred(s78v);
            if (lane == 0) {
                stcg(&g_Y[OY3 + l], y3n);
                stcg(&g_Y[OY4 + l], y4n);
                stcg(&g_s78s[l], s78s);
                stcg(&g_t[l], y3n - y4n + s78s);
            }
        }
    } else {
        if (POW && wId < 8) {
            const int base = (blk - 128)*40 + wId*5;
#pragma unroll
            for (int r = 0; r < 5; r++) {
                const int u = base + r;
                float ru = ldcg(&g_X[OX_RU + u]) * inv;
                float rd = ldcg(&g_X[OX_RD + u]) * inv;
                if (lane == 0) {
                    float p = ldcg(&g_X[OX_P + u]) * inv;
                    stcg(&g_Y[OY1 + u], p + ru);
                    stcg(&g_Y[OY2 + u], rd - p);
                }
                if (lane < cS) {
                    float pu = ldcg(&g_X[OX_PU + u*cS + lane]) * inv;
                    float pd = ldcg(&g_X[OX_PD + u*cS + lane]) * inv;
                    stcg(&g_Y[OY5 + u*cS + lane], pu - ru);
                    stcg(&g_Y[OY6 + u*cS + lane], pd - rd);
                }
            }
        }
        if (blk == 128 && wId == 15) {
            float sp = 0.f;
            for (int b = lane; b < 80; b += 32) sp += ldcg(&g_part_p[b]);
            sp = wallred(sp);
            float se = 0.f;
            for (int b = 80 + lane; b < NB; b += 32) se += ldcg(&g_part_e[b]);
            se = wallred(se);
            int s = lane & 15, h = lane >> 4;
            float sc = 0.f;
#pragma unroll
            for (int b = h*40; b < h*40 + 40; b++) sc += ldcg(&g_part_c[b*cS + s]);
            sc += __shfl_xor_sync(0xffffffffu, sc, 16);
            float ae2 = sc + se;
            float z2n = 0.f;
            if (lane < cS) {
                z2n = POW ? (ae2 * inv) : (ldcg(&g_z2[lane]) + sig*(ae2 - g_beq2[lane]));
                stcg(&g_z2[lane], z2n);
            }
            float zsum = wallred((lane < cS) ? z2n : 0.f);
            if (lane == 0) {
                float z1n = POW ? (sp * inv) : (ldcg(&g_z1) + sig*(sp - g_beq1));
                stcg(&g_z1, z1n);
                stcg(&g_z2sum, zsum);
            }
        }
    }
}

// ---------------- main persistent kernel ----------------
__global__ void __launch_bounds__(NT, 1)
opf_kernel(const float* __restrict__ w_scen, const float* __restrict__ Pmax,
           const float* __restrict__ Cost, const float* __restrict__ Cru,
           const float* __restrict__ Crd, const float* __restrict__ PTDF,
           const float* __restrict__ node_G, const float* __restrict__ node_W,
           const float* __restrict__ Pd, const float* __restrict__ w_exp,
           const float* __restrict__ Cap, float* __restrict__ out)
{
    __shared__ __align__(16) float dsh_t[cS*cU];   // phase B staging (10.2 KB)
    __shared__ float sdsh[cN];
    __shared__ float psh[cU];
    __shared__ float s78s_sh[cL];
    __shared__ float sA[16*34];
    __shared__ float sB[16*19];
    __shared__ float shn[16];
    __shared__ float shp[2], shc[2*cS], sh8[8], sh8b[8];

    const int blk  = blockIdx.x;
    const int tid  = blk * NT + threadIdx.x;
    const int wId  = threadIdx.x >> 5;
    const int lane = threadIdx.x & 31;
    const int gw   = (wId < 8) ? (blk * 8 + wId) : 0x7fffffff;
    unsigned rnd;
    {
        unsigned e;
        asm volatile("ld.global.cg.u32 %0, [%1];" : "=r"(e) : "l"(&g_epoch));
        rnd = e;
    }

    // ---- setup 1: index extraction + equality rhs ----
    if (gw < cU) {
        int u = gw, f = -1;
        for (int n = lane; n < cN; n += 32)
            if (node_G[n * cU + u] != 0.f) f = n;
#pragma unroll
        for (int o = 16; o; o >>= 1) f = max(f, __shfl_xor_sync(0xffffffffu, f, o));
        if (lane == 0) __stcg(&g_gidx[u], f);
    } else if (gw < cU + cW) {
        int w = gw - cU, f = -1;
        for (int n = lane; n < cN; n += 32)
            if (node_W[n * cW + w] != 0.f) f = n;
#pragma unroll
        for (int o = 16; o; o >>= 1) f = max(f, __shfl_xor_sync(0xffffffffu, f, o));
        if (lane == 0) __stcg(&g_widx[w], f);
    } else if (gw == cU + cW) {
        float a = 0.f;
        for (int n = lane; n < cN; n += 32) a += Pd[n];
        for (int w = lane; w < cW; w += 32) a -= w_exp[w];
        a = wallred(a);
        if (lane == 0) stcg(&g_beq1, a);
    } else if (gw > cU + cW && gw <= cU + cW + cS) {
        int s = gw - (cU + cW + 1);
        float a = 0.f;
        for (int w = lane; w < cW; w += 32) a += w_scen[s * cW + w];
        a = wallred(a);
        if (lane == 0) stcg(&g_beq2[s], -a);
    }
    gsync(++rnd);

    // ---- setup 2: materialize matrices, rhs vectors, init power-iter state ----
    for (int i = tid; i < cL * cU; i += NTH) {
        int l = i / cU, u = i - l * cU;
        float v = PTDF[l * cN + __ldcg(&g_gidx[u])];
        g_Hg[l * cU + u] = v;
        g_HgT[u * cL + l] = v;
    }
    for (int i = tid; i < cN * cL; i += NTH) {
        int n = i >> 9, l = i & (cL - 1);
        g_PTT[i] = PTDF[l * cN + n];
    }
    if (gw < cL) {
        int l = gw;
        const float* pr = PTDF + l * cN;
        float a = 0.f;
        for (int n = lane; n < cN; n += 32) a -= pr[n] * Pd[n];
        float hw0 = pr[__ldcg(&g_widx[lane])];
        float hw1 = pr[__ldcg(&g_widx[lane + 32])];
        a += hw0 * w_exp[lane] + hw1 * w_exp[lane + 32];
        float cf = wallred(a);
        float cap = Cap[l];
        float c3 = cap - cf, c4 = cap + cf;
        if (lane == 0) { g_c3[l] = c3; g_c4[l] = c4; }
        float bws = 0.f;
#pragma unroll 4
        for (int w = 0; w < 32; w++) {
            float h0 = __shfl_sync(0xffffffffu, hw0, w);
            float h1 = __shfl_sync(0xffffffffu, hw1, w);
            if (lane < cS)
                bws += h0 * w_scen[lane * cW + w] + h1 * w_scen[lane * cW + w + 32];
        }
        if (lane < cS) {
            g_b7[l * cS + lane] = c3 - bws;
            g_b8[l * cS + lane] = c4 + bws;
        }
    }
    // init v0 = ones + its eq partials
    for (int i = tid; i < XTOT; i += NTH) stcg(&g_X[i], 1.f);
    for (int i = tid; i < cU; i += NTH)    stcg(&g_XBP[i], 1.f);
    for (int i = tid; i < cU*cS; i += NTH) stcg(&g_XBC[i], 0.f);
    for (int i = tid; i < cN; i += NTH)    stcg(&g_XBE[i], 0.f);
    if (tid < NB) {
        stcg(&g_part_ss[tid], (tid == 0) ? 1.f : 0.f);
        stcg(&g_part_e[tid], 0.f);
        stcg(&g_part_p[tid], (tid < 80) ? 2.f : 0.f);
    }
    for (int i = tid; i < 80*cS; i += NTH) stcg(&g_part_c[i], 0.f);
    gsync(++rnd);

    // ---- power iteration for ||A|| (31 fused B/A pairs; norm folded into B) ----
#pragma unroll 1
    for (int it = 0; it <= NPOWER; it++) {
        phaseB<true>(blk, wId, lane, 0.f, PTDF, dsh_t, sdsh, psh, sB);
        gsync(++rnd);
        phaseA<true>(blk, wId, lane, 0.f, Cost, Cru, Crd, Pmax,
                     sA, shn, shp, shc, sh8, sh8b, s78s_sh);
        gsync(++rnd);
    }

    // ---- reset state + compute tau ----
    for (int i = tid; i < XTOT; i += NTH) stcg(&g_X[i], 0.f);
    for (int i = tid; i < cU; i += NTH)    stcg(&g_XBP[i], 0.f);
    for (int i = tid; i < cU*cS; i += NTH) stcg(&g_XBC[i], 0.f);
    for (int i = tid; i < cN; i += NTH)    stcg(&g_XBE[i], 0.f);
    for (int i = tid; i < YTOT; i += NTH) stcg(&g_Y[i], 0.f);
    for (int i = tid; i < cL * cS; i += NTH) stcg(&g_s78[i], 0.f);
    for (int i = tid; i < cL; i += NTH) { stcg(&g_s78s[i], 0.f); stcg(&g_t[i], 0.f); }
    if (tid == 0) {
        float a = 0.f;
        for (int b = 0; b < NB; b++) a += ldcg(&g_part_ss[b]);
        float Lop = sqrtf(sqrtf(a));
        stcg(&g_tau, 0.9f / Lop);
        stcg(&g_z1, 0.f); stcg(&g_z2sum, 0.f);
    }
    if (tid < cS) stcg(&g_z2[tid], 0.f);
    gsync(++rnd);

    const float tau = ldcg(&g_tau);

    // ---- PDHG main loop (skip output-irrelevant final phase B) ----
#pragma unroll 1
    for (int it = 0; it < NITERS-1; it++) {
        phaseA<false>(blk, wId, lane, tau, Cost, Cru, Crd, Pmax,
                      sA, shn, shp, shc, sh8, sh8b, s78s_sh);
        gsync(++rnd);
        phaseB<false>(blk, wId, lane, tau, PTDF, dsh_t, sdsh, psh, sB);
        gsync(++rnd);
    }
    phaseA<false>(blk, wId, lane, tau, Cost, Cru, Crd, Pmax,
                  sA, shn, shp, shc, sh8, sh8b, s78s_sh);
    gsync(++rnd);

    // ---- output ----
    if (blk < 128 && wId < 4) {
        int l = blk*4 + wId;
        const float* hr = g_Hg + (size_t)l * cU;
        float a = 0.f;
        for (int u = lane; u < cU; u += 32) a = fmaf(hr[u], ldcg(&g_X[OX_P + u]), a);
        a = wallred(a);
        if (lane == 0) {
            out[5600 + l] = g_c3[l] - a;   // f_up = Cap - flow
            out[6112 + l] = g_c4[l] + a;   // f_down = Cap + flow
        }
    } else if ((blk < 128 && wId == 4) || (blk < 32 && wId == 5)) {
        int u = (wId == 4) ? blk : (128 + blk);
        if (lane == 0) {
            out[u]       = ldcg(&g_X[OX_P + u]);
            out[160 + u] = ldcg(&g_X[OX_RU + u]);
            out[320 + u] = ldcg(&g_X[OX_RD + u]);
        }
        if (lane < cS) {
            out[480 + u*cS + lane]  = ldcg(&g_X[OX_PU + u*cS + lane]);
            out[3040 + u*cS + lane] = ldcg(&g_X[OX_PD + u*cS + lane]);
        }
    } else if (blk == 131 && wId == 15) {
        float a = 0.f;
        for (int i = lane; i < cU; i += 32)
            a += Cost[i] * ldcg(&g_X[OX_P + i]) + Cru[i] * ldcg(&g_X[OX_RU + i])
               + Crd[i] * ldcg(&g_X[OX_RD + i]);
        for (int i = lane; i < cN; i += 32)
            a += CVIOL * (ldcg(&g_X[OX_SU + i]) + ldcg(&g_X[OX_SD + i]));
        a = wallred(a);
        if (lane == 0) out[6624] = a;
    }

    // persist the barrier epoch for the next (stream-ordered) launch
    if (blk == 0 && threadIdx.x == 0) {
        asm volatile("st.global.cg.u32 [%0], %1;" :: "l"(&g_epoch), "r"(rnd) : "memory");
    }
}

extern "C" void kernel_launch(void* const* d_in, const int* in_sizes, int n_in,
                              void* d_out, int out_size) {
    const float* w_scen = (const float*)d_in[0];
    const float* Pmax   = (const float*)d_in[1];
    const float* Cost   = (const float*)d_in[2];
    const float* Cru    = (const float*)d_in[3];
    const float* Crd    = (const float*)d_in[4];
    const float* PTDF   = (const float*)d_in[5];
    const float* node_G = (const float*)d_in[6];
    const float* node_W = (const float*)d_in[7];
    // d_in[8] = node_L (identity, unused)
    const float* Pd     = (const float*)d_in[9];
    const float* w_exp  = (const float*)d_in[10];
    const float* Cap    = (const float*)d_in[11];
    float* out = (float*)d_out;
    (void)in_sizes; (void)n_in; (void)out_size;

    opf_kernel<<<NB, NT>>>(w_scen, Pmax, Cost, Cru, Crd, PTDF,
                           node_G, node_W, Pd, w_exp, Cap, out);
}